// round 4
// baseline (speedup 1.0000x reference)
#include <cuda_runtime.h>

// ---------------------------------------------------------------------------
// FlashMultiHeadAttention: x -> QKV GEMM -> RoPE -> flash attention -> proj
// B=4, T=2048, D=1024, H=16, DH=64, all fp32.
// ---------------------------------------------------------------------------

constexpr int Bb  = 4;
constexpr int T   = 2048;
constexpr int D   = 1024;
constexpr int H   = 16;
constexpr int DH  = 64;
constexpr int BHn = Bb * H;       // 64
constexpr int M   = Bb * T;       // 8192 rows
constexpr int KD  = D;            // 1024 (reduction dim of both GEMMs)
constexpr int NQKV = 3 * D;       // 3072

// Scratch (static __device__ allocation, allowed by harness rules)
__device__ float g_Q[(size_t)BHn * T * DH];   // [bh][t][d]
__device__ float g_K[(size_t)BHn * T * DH];
__device__ float g_V[(size_t)BHn * T * DH];
__device__ float g_AO[(size_t)M * D];         // attention output [b,t,h*dh]

// ---------------------------------------------------------------------------
// SGEMM: C[M,N] = A[M,KD] @ Bw[KD,N] + bias[N]
// MODE 0: A = Ain (=x), scatter result into g_Q/g_K/g_V per-head layout
// MODE 1: A = g_AO, write Cout row-major (d_out)
// 128x128x8 tiles, 256 threads, 8x8 per-thread micro-tile.
// ---------------------------------------------------------------------------
template <int MODE>
__global__ __launch_bounds__(256, 2)
void sgemm_kernel(const float* __restrict__ Ain,
                  const float* __restrict__ Bw,
                  const float* __restrict__ bias,
                  float* __restrict__ Cout,
                  int N)
{
    constexpr int BM = 128, BN = 128, BK = 8;
    __shared__ float As[BK][BM + 4];   // A stored transposed: As[k][m], pad kills store conflicts
    __shared__ float Bs[BK][BN];

    const float* A = (MODE == 1) ? g_AO : Ain;

    const int tid = threadIdx.x;
    const int m0 = blockIdx.y * BM;
    const int n0 = blockIdx.x * BN;
    const int tx = tid & 15;
    const int ty = tid >> 4;

    const int a_row = tid >> 1;          // 0..127
    const int a_col = (tid & 1) * 4;     // 0 or 4
    const int b_row = tid >> 5;          // 0..7
    const int b_col = (tid & 31) * 4;    // 0..124

    const float* Aptr = A + (size_t)(m0 + a_row) * KD + a_col;
    const float* Bptr = Bw + (size_t)b_row * N + n0 + b_col;

    float acc[8][8];
#pragma unroll
    for (int i = 0; i < 8; i++)
#pragma unroll
        for (int j = 0; j < 8; j++) acc[i][j] = 0.f;

    for (int k0 = 0; k0 < KD; k0 += BK) {
        float4 av = *(const float4*)Aptr;
        float4 bv = *(const float4*)Bptr;
        __syncthreads();
        As[a_col + 0][a_row] = av.x;
        As[a_col + 1][a_row] = av.y;
        As[a_col + 2][a_row] = av.z;
        As[a_col + 3][a_row] = av.w;
        *(float4*)&Bs[b_row][b_col] = bv;
        __syncthreads();
        Aptr += BK;
        Bptr += (size_t)BK * N;

#pragma unroll
        for (int kk = 0; kk < BK; kk++) {
            float af[8], bf[8];
            *(float4*)&af[0] = *(const float4*)&As[kk][ty * 8];
            *(float4*)&af[4] = *(const float4*)&As[kk][ty * 8 + 4];
            *(float4*)&bf[0] = *(const float4*)&Bs[kk][tx * 8];
            *(float4*)&bf[4] = *(const float4*)&Bs[kk][tx * 8 + 4];
#pragma unroll
            for (int i = 0; i < 8; i++)
#pragma unroll
                for (int j = 0; j < 8; j++)
                    acc[i][j] += af[i] * bf[j];
        }
    }

    float bfr[8];
#pragma unroll
    for (int j = 0; j < 8; j++) bfr[j] = bias[n0 + tx * 8 + j];

#pragma unroll
    for (int i = 0; i < 8; i++) {
        const int m = m0 + ty * 8 + i;
#pragma unroll
        for (int j = 0; j < 8; j++) {
            const int n = n0 + tx * 8 + j;
            const float v = acc[i][j] + bfr[j];
            if (MODE == 1) {
                Cout[(size_t)m * N + n] = v;
            } else {
                // n -> (sel, h, dd); m -> (b, t). Scatter to [bh][t][dd].
                const int sel = n >> 10;
                const int rem = n & 1023;
                const int h   = rem >> 6;
                const int dd  = rem & 63;
                const int b   = m >> 11;
                const int t   = m & 2047;
                float* P = (sel == 0) ? g_Q : (sel == 1) ? g_K : g_V;
                P[(((size_t)(b * H + h)) * T + t) * DH + dd] = v;
            }
        }
    }
}

// ---------------------------------------------------------------------------
// RoPE applied in-place to g_Q and g_K. Q additionally pre-scaled by DH^-0.5.
// One thread handles the (d, d+32) rotation pair. cos[t,d] == cos[t,d+32].
// Total threads = 2 * BHn * T * 32 = 2^23.
// ---------------------------------------------------------------------------
__global__ void rope_kernel(const float* __restrict__ cosT,
                            const float* __restrict__ sinT)
{
    const int idx = blockIdx.x * blockDim.x + threadIdx.x;
    const int d   = idx & 31;
    const int t   = (idx >> 5) & (T - 1);
    const int bh  = (idx >> 16) & (BHn - 1);
    const int arr = idx >> 22;          // 0 = Q, 1 = K
    float* P = arr ? g_K : g_Q;
    const size_t base = ((size_t)bh * T + t) * DH;
    const float u1 = P[base + d];
    const float u2 = P[base + d + 32];
    const float c  = cosT[t * DH + d];
    const float s  = sinT[t * DH + d];
    float o1 = u1 * c - u2 * s;
    float o2 = u2 * c + u1 * s;
    if (arr == 0) { o1 *= 0.125f; o2 *= 0.125f; }   // DH^-0.5 folded into Q
    P[base + d]      = o1;
    P[base + d + 32] = o2;
}

// ---------------------------------------------------------------------------
// Flash attention. One block: 128 query rows of one (b,h); loops over 64-row
// key tiles. 256 threads; thread (tx=tid&15, ty=tid>>4) owns rows ty*8..+7
// and columns {tx + 16*j, j=0..3} (strided -> conflict-free smem access).
// Online softmax state replicated across each 16-lane row group via shfl_xor.
// ---------------------------------------------------------------------------
constexpr int FBM = 128, FBN = 64;
constexpr int LDQ = 65, LDK = 65, LDV = 64, LDP = 65;
constexpr int SMEM_FLASH = (FBM * LDQ + FBN * LDK + FBN * LDV + FBM * LDP) * 4; // 99584 B

__global__ __launch_bounds__(256, 2)
void flash_kernel()
{
    extern __shared__ float sm[];
    float* Qs  = sm;                    // [FBM][LDQ]
    float* Kts = Qs + FBM * LDQ;        // [DH][LDK]  (K transposed: Kts[d][n])
    float* Vs  = Kts + FBN * LDK;       // [FBN][LDV] (Vs[n][d])
    float* Ps  = Vs + FBN * LDV;        // [FBM][LDP]

    const int tid = threadIdx.x;
    const int bh  = blockIdx.y;
    const int q0  = blockIdx.x * FBM;
    const int tx  = tid & 15;
    const int ty  = tid >> 4;
    const int r0  = ty * 8;

    const float* Qg = g_Q + ((size_t)bh * T + q0) * DH;
    const float* Kg = g_K + (size_t)bh * T * DH;
    const float* Vg = g_V + (size_t)bh * T * DH;

    // Load Q tile (128x64): 8 float4 per thread, scalar smem stores (ld=65)
#pragma unroll
    for (int i = 0; i < 8; i++) {
        const int idx = tid * 4 + i * 1024;
        const int r = idx >> 6, d = idx & 63;
        const float4 v = *(const float4*)(Qg + idx);
        Qs[r * LDQ + d + 0] = v.x;
        Qs[r * LDQ + d + 1] = v.y;
        Qs[r * LDQ + d + 2] = v.z;
        Qs[r * LDQ + d + 3] = v.w;
    }

    float m_i[8], l_i[8], o[8][4];
#pragma unroll
    for (int i = 0; i < 8; i++) {
        m_i[i] = -1e30f;
        l_i[i] = 0.f;
#pragma unroll
        for (int j = 0; j < 4; j++) o[i][j] = 0.f;
    }

    for (int n0 = 0; n0 < T; n0 += FBN) {
        __syncthreads();   // prev iteration's Kts/Vs/Ps reads complete
        // Load K tile transposed + V tile (each 64x64): 4 float4 per thread
#pragma unroll
        for (int i = 0; i < 4; i++) {
            const int idx = tid * 4 + i * 1024;
            const int n = idx >> 6, d = idx & 63;
            const float4 kv = *(const float4*)(Kg + (size_t)n0 * DH + idx);
            Kts[(d + 0) * LDK + n] = kv.x;
            Kts[(d + 1) * LDK + n] = kv.y;
            Kts[(d + 2) * LDK + n] = kv.z;
            Kts[(d + 3) * LDK + n] = kv.w;
            const float4 vv = *(const float4*)(Vg + (size_t)n0 * DH + idx);
            *(float4*)&Vs[n * LDV + d] = vv;
        }
        __syncthreads();

        // S = Q @ K^T  (Q already carries the 1/sqrt(DH) scale)
        float s[8][4];
#pragma unroll
        for (int i = 0; i < 8; i++)
#pragma unroll
            for (int j = 0; j < 4; j++) s[i][j] = 0.f;

#pragma unroll 4
        for (int k = 0; k < DH; k++) {
            float q[8], kf[4];
#pragma unroll
            for (int i = 0; i < 8; i++) q[i] = Qs[(r0 + i) * LDQ + k];
#pragma unroll
            for (int j = 0; j < 4; j++) kf[j] = Kts[k * LDK + tx + 16 * j];
#pragma unroll
            for (int i = 0; i < 8; i++)
#pragma unroll
                for (int j = 0; j < 4; j++)
                    s[i][j] += q[i] * kf[j];
        }

        // Online softmax (row groups of 16 lanes; xor masks <16 stay in-group)
#pragma unroll
        for (int i = 0; i < 8; i++) {
            float mx = fmaxf(fmaxf(s[i][0], s[i][1]), fmaxf(s[i][2], s[i][3]));
#pragma unroll
            for (int off = 1; off < 16; off <<= 1)
                mx = fmaxf(mx, __shfl_xor_sync(0xffffffffu, mx, off));
            const float mnew = fmaxf(m_i[i], mx);
            const float corr = __expf(m_i[i] - mnew);
            m_i[i] = mnew;
            float rs = 0.f;
#pragma unroll
            for (int j = 0; j < 4; j++) {
                s[i][j] = __expf(s[i][j] - mnew);
                rs += s[i][j];
            }
#pragma unroll
            for (int off = 1; off < 16; off <<= 1)
                rs += __shfl_xor_sync(0xffffffffu, rs, off);
            l_i[i] = l_i[i] * corr + rs;
#pragma unroll
            for (int j = 0; j < 4; j++) o[i][j] *= corr;
        }

        // Stage P to smem, then O += P @ V
#pragma unroll
        for (int i = 0; i < 8; i++)
#pragma unroll
            for (int j = 0; j < 4; j++)
                Ps[(r0 + i) * LDP + tx + 16 * j] = s[i][j];
        __syncthreads();

#pragma unroll 4
        for (int k = 0; k < FBN; k++) {
            float p[8], v[4];
#pragma unroll
            for (int i = 0; i < 8; i++) p[i] = Ps[(r0 + i) * LDP + k];
#pragma unroll
            for (int j = 0; j < 4; j++) v[j] = Vs[k * LDV + tx + 16 * j];
#pragma unroll
            for (int i = 0; i < 8; i++)
#pragma unroll
                for (int j = 0; j < 4; j++)
                    o[i][j] += p[i] * v[j];
        }
    }

    // Epilogue: normalize and write to [b, t, h*DH + c]
    const int b = bh >> 4;
    const int h = bh & 15;
#pragma unroll
    for (int i = 0; i < 8; i++) {
        const float inv = 1.f / l_i[i];
        const int t = q0 + r0 + i;
        const size_t rowbase = ((size_t)b * T + t) * D + h * DH;
#pragma unroll
        for (int j = 0; j < 4; j++)
            g_AO[rowbase + tx + 16 * j] = o[i][j] * inv;
    }
}

// ---------------------------------------------------------------------------
// Launch: qkv gemm -> rope -> flash -> proj gemm. Graph-capturable (launches
// only; no sync/alloc/memcpy). cudaFuncSetAttribute is idempotent, non-stream.
// ---------------------------------------------------------------------------
extern "C" void kernel_launch(void* const* d_in, const int* in_sizes, int n_in,
                              void* d_out, int out_size)
{
    (void)in_sizes; (void)n_in; (void)out_size;
    const float* x     = (const float*)d_in[0];
    const float* Wqkv  = (const float*)d_in[1];
    const float* bqkv  = (const float*)d_in[2];
    const float* Wproj = (const float*)d_in[3];
    const float* bproj = (const float*)d_in[4];
    const float* cosT  = (const float*)d_in[5];
    const float* sinT  = (const float*)d_in[6];
    float* out = (float*)d_out;

    sgemm_kernel<0><<<dim3(NQKV / 128, M / 128), 256>>>(x, Wqkv, bqkv, nullptr, NQKV);
    rope_kernel<<<(2 * BHn * T * 32) / 256, 256>>>(cosT, sinT);
    cudaFuncSetAttribute(flash_kernel, cudaFuncAttributeMaxDynamicSharedMemorySize, SMEM_FLASH);
    flash_kernel<<<dim3(T / FBM, BHn), 256, SMEM_FLASH>>>();
    sgemm_kernel<1><<<dim3(D / 128, M / 128), 256>>>(nullptr, Wproj, bproj, out, D);
}

// round 6
// speedup vs baseline: 2.5815x; 2.5815x over previous
#include <cuda_runtime.h>
#include <cuda_bf16.h>

// ---------------------------------------------------------------------------
// FlashMultiHeadAttention on tensor pipe: bf16 split-precision (hi+lo) HMMA.
// B=4, T=2048, D=1024, H=16, DH=64. Every matmul = 3x bf16 mma per k16 step.
// NOTE: all __device__ scratch arrays are referenced ONLY from device code
// (template-selected). Host passes only harness pointers.
// ---------------------------------------------------------------------------

constexpr int Bb  = 4;
constexpr int T   = 2048;
constexpr int Dm  = 1024;
constexpr int H   = 16;
constexpr int DH  = 64;
constexpr int BHn = Bb * H;       // 64
constexpr int M   = Bb * T;       // 8192
constexpr int KD  = Dm;           // 1024
constexpr int NQKV = 3 * Dm;      // 3072

// ---- scratch (__device__ statics) ------------------------------------------
__device__ __align__(256) __nv_bfloat16 g_xh[(size_t)M * KD],     g_xl[(size_t)M * KD];
__device__ __align__(256) __nv_bfloat16 g_w1h[(size_t)KD * NQKV], g_w1l[(size_t)KD * NQKV];
__device__ __align__(256) __nv_bfloat16 g_w2h[(size_t)KD * Dm],   g_w2l[(size_t)KD * Dm];
__device__ __align__(256) float         g_Qf[(size_t)BHn * T * DH], g_Kf[(size_t)BHn * T * DH];
__device__ __align__(256) __nv_bfloat16 g_Qh[(size_t)BHn * T * DH], g_Ql[(size_t)BHn * T * DH];
__device__ __align__(256) __nv_bfloat16 g_Kh[(size_t)BHn * T * DH], g_Kl[(size_t)BHn * T * DH];
__device__ __align__(256) __nv_bfloat16 g_Vh[(size_t)BHn * T * DH], g_Vl[(size_t)BHn * T * DH];
__device__ __align__(256) __nv_bfloat16 g_AOh[(size_t)M * Dm],      g_AOl[(size_t)M * Dm];

// ---- PTX helpers -----------------------------------------------------------
__device__ __forceinline__ void cp16(unsigned dst, const void* src) {
    asm volatile("cp.async.cg.shared.global [%0], [%1], 16;\n" :: "r"(dst), "l"(src));
}
#define CP_COMMIT()  asm volatile("cp.async.commit_group;\n" ::: "memory")
#define CP_WAIT1()   asm volatile("cp.async.wait_group 1;\n" ::: "memory")

__device__ __forceinline__ void ldsm4(unsigned* r, unsigned a) {
    asm volatile("ldmatrix.sync.aligned.m8n8.x4.shared.b16 {%0,%1,%2,%3}, [%4];\n"
                 : "=r"(r[0]), "=r"(r[1]), "=r"(r[2]), "=r"(r[3]) : "r"(a));
}
__device__ __forceinline__ void ldsm4t(unsigned* r, unsigned a) {
    asm volatile("ldmatrix.sync.aligned.m8n8.x4.trans.shared.b16 {%0,%1,%2,%3}, [%4];\n"
                 : "=r"(r[0]), "=r"(r[1]), "=r"(r[2]), "=r"(r[3]) : "r"(a));
}
__device__ __forceinline__ void mma16816(float* c, const unsigned* a, const unsigned* b) {
    asm volatile("mma.sync.aligned.m16n8k16.row.col.f32.bf16.bf16.f32 "
                 "{%0,%1,%2,%3}, {%4,%5,%6,%7}, {%8,%9}, {%0,%1,%2,%3};\n"
                 : "+f"(c[0]), "+f"(c[1]), "+f"(c[2]), "+f"(c[3])
                 : "r"(a[0]), "r"(a[1]), "r"(a[2]), "r"(a[3]), "r"(b[0]), "r"(b[1]));
}
__device__ __forceinline__ unsigned pack2f(float a, float b) {
    __nv_bfloat162 t = __floats2bfloat162_rn(a, b);
    return *reinterpret_cast<unsigned*>(&t);
}

// ---------------------------------------------------------------------------
// Elementwise fp32 -> (hi, lo) bf16 split. DST: 0 = x, 1 = Wqkv, 2 = Wproj.
// Destination arrays resolved in DEVICE code (host cannot take g_* addresses).
// ---------------------------------------------------------------------------
template <int DST>
__global__ void split4_kernel(const float4* __restrict__ src, int n4)
{
    __nv_bfloat162* dh = reinterpret_cast<__nv_bfloat162*>(
        DST == 0 ? g_xh : DST == 1 ? g_w1h : g_w2h);
    __nv_bfloat162* dl = reinterpret_cast<__nv_bfloat162*>(
        DST == 0 ? g_xl : DST == 1 ? g_w1l : g_w2l);
    int i = blockIdx.x * blockDim.x + threadIdx.x;
    if (i >= n4) return;
    float4 v = src[i];
    __nv_bfloat16 h0 = __float2bfloat16_rn(v.x), h1 = __float2bfloat16_rn(v.y);
    __nv_bfloat16 h2 = __float2bfloat16_rn(v.z), h3 = __float2bfloat16_rn(v.w);
    dh[2 * i]     = __halves2bfloat162(h0, h1);
    dh[2 * i + 1] = __halves2bfloat162(h2, h3);
    dl[2 * i]     = __floats2bfloat162_rn(v.x - __bfloat162float(h0), v.y - __bfloat162float(h1));
    dl[2 * i + 1] = __floats2bfloat162_rn(v.z - __bfloat162float(h2), v.w - __bfloat162float(h3));
}

// ---------------------------------------------------------------------------
// GEMM: C[M,N] = A[M,1024] @ B[1024,N] + bias, split-bf16 HMMA.
// 128x128x32 tiles, 256 thr (8 warps 2x4), warp tile 64x32, cp.async 2-stage.
// MODE 0: A=x, B=Wqkv, scatter -> Qf/Kf fp32 + V split.  MODE 1: A=AO, B=Wproj,
// fp32 row-major out. All scratch arrays resolved in device code.
// ---------------------------------------------------------------------------
constexpr int APITCH = 40;    // halves/row; bank base 20r mod 32 distinct
constexpr int BPITCH = 136;   // halves/row; bank base 4r mod 32 distinct
constexpr int A_ELE  = 128 * APITCH;
constexpr int B_ELE  = 32 * BPITCH;
constexpr int GSTAGE = 2 * A_ELE + 2 * B_ELE;       // halves per stage
constexpr int GSMEM  = 2 * GSTAGE * 2;              // bytes (75776)

template <int MODE>
__global__ __launch_bounds__(256, 1)
void gemm_bf16(const float* __restrict__ bias, float* __restrict__ Cout, int N)
{
    const __nv_bfloat16* __restrict__ Ah = (MODE == 0) ? g_xh  : g_AOh;
    const __nv_bfloat16* __restrict__ Al = (MODE == 0) ? g_xl  : g_AOl;
    const __nv_bfloat16* __restrict__ Bh = (MODE == 0) ? g_w1h : g_w2h;
    const __nv_bfloat16* __restrict__ Bl = (MODE == 0) ? g_w1l : g_w2l;

    extern __shared__ __nv_bfloat16 gsm[];
    const int tid = threadIdx.x;
    const int m0 = blockIdx.y * 128, n0 = blockIdx.x * 128;
    const int wid = tid >> 5, lane = tid & 31;
    const int wm = wid >> 2, wn = wid & 3;
    const int g = lane >> 2, q = lane & 3;
    const int seg = lane >> 3, l7 = lane & 7;
    const unsigned sbase = (unsigned)__cvta_generic_to_shared(gsm);

    auto loadStage = [&](int stage, int k0) {
        unsigned sb = sbase + stage * GSTAGE * 2;
#pragma unroll
        for (int i = 0; i < 4; i++) {            // A: 1024 16B chunks
            int cid = tid + 256 * i;
            int prec = cid >> 9;
            int r = (cid & 511) >> 2, c = cid & 3;
            const __nv_bfloat16* src = (prec ? Al : Ah) + (size_t)(m0 + r) * KD + k0 + c * 8;
            cp16(sb + (prec * A_ELE + r * APITCH + c * 8) * 2, src);
        }
#pragma unroll
        for (int i = 0; i < 4; i++) {            // B: 1024 16B chunks
            int cid = tid + 256 * i;
            int prec = cid >> 9;
            int rr = (cid & 511) >> 4, cc = cid & 15;
            const __nv_bfloat16* src = (prec ? Bl : Bh) + (size_t)(k0 + rr) * N + n0 + cc * 8;
            cp16(sb + (2 * A_ELE + prec * B_ELE + rr * BPITCH + cc * 8) * 2, src);
        }
    };

    float acc[4][4][4];
#pragma unroll
    for (int a = 0; a < 4; a++)
#pragma unroll
        for (int b = 0; b < 4; b++)
#pragma unroll
            for (int c = 0; c < 4; c++) acc[a][b][c] = 0.f;

    loadStage(0, 0);
    CP_COMMIT();
    for (int it = 0; it < KD / 32; ++it) {
        if (it + 1 < KD / 32) loadStage((it + 1) & 1, (it + 1) * 32);
        CP_COMMIT();
        CP_WAIT1();
        __syncthreads();
        unsigned sb = sbase + (it & 1) * GSTAGE * 2;
        unsigned bB = sb + 2 * A_ELE * 2;
#pragma unroll
        for (int ks = 0; ks < 2; ks++) {
            const int kb = ks * 16;
            unsigned ah[4][4], al[4][4];
#pragma unroll
            for (int mt = 0; mt < 4; mt++) {     // A frag: seg1->row+8, seg2->k+8
                int r2 = wm * 64 + mt * 16 + l7 + (seg & 1) * 8;
                int c2 = kb + ((seg >> 1) & 1) * 8;
                unsigned ad = sb + (r2 * APITCH + c2) * 2;
                ldsm4(ah[mt], ad);
                ldsm4(al[mt], ad + A_ELE * 2);
            }
            unsigned bhf[2][4], blf[2][4];
#pragma unroll
            for (int np = 0; np < 2; np++) {     // B frag (trans): seg1->k+8, seg2->n+8
                int rr = kb + l7 + (seg & 1) * 8;
                int cc = wn * 32 + np * 16 + ((seg >> 1) & 1) * 8;
                unsigned bd = bB + (rr * BPITCH + cc) * 2;
                ldsm4t(bhf[np], bd);
                ldsm4t(blf[np], bd + B_ELE * 2);
            }
#pragma unroll
            for (int mt = 0; mt < 4; mt++)
#pragma unroll
                for (int nt = 0; nt < 4; nt++) {
                    const unsigned* b2h = &bhf[nt >> 1][(nt & 1) * 2];
                    const unsigned* b2l = &blf[nt >> 1][(nt & 1) * 2];
                    mma16816(acc[mt][nt], ah[mt], b2h);   // hi*hi
                    mma16816(acc[mt][nt], ah[mt], b2l);   // hi*lo
                    mma16816(acc[mt][nt], al[mt], b2h);   // lo*hi
                }
        }
        __syncthreads();
    }

#pragma unroll
    for (int mt = 0; mt < 4; mt++)
#pragma unroll
        for (int i = 0; i < 2; i++) {
            const int row = m0 + wm * 64 + mt * 16 + g + i * 8;
#pragma unroll
            for (int nt = 0; nt < 4; nt++)
#pragma unroll
                for (int j = 0; j < 2; j++) {
                    const int col = n0 + wn * 32 + nt * 8 + 2 * q + j;
                    const float v = acc[mt][nt][i * 2 + j] + bias[col];
                    if (MODE == 1) {
                        Cout[(size_t)row * N + col] = v;
                    } else {
                        const int sel = col >> 10;
                        const int rem = col & 1023;
                        const int hh = rem >> 6, dd = rem & 63;
                        const int b = row >> 11, t = row & 2047;
                        const size_t o = (((size_t)(b * H + hh)) * T + t) * DH + dd;
                        if (sel == 0)      g_Qf[o] = v;
                        else if (sel == 1) g_Kf[o] = v;
                        else {
                            __nv_bfloat16 h = __float2bfloat16_rn(v);
                            g_Vh[o] = h;
                            g_Vl[o] = __float2bfloat16_rn(v - __bfloat162float(h));
                        }
                    }
                }
        }
}

// ---------------------------------------------------------------------------
// RoPE on fp32 Q/K; outputs split bf16 hi/lo. Q pre-scaled by DH^-0.5.
// ---------------------------------------------------------------------------
__global__ void rope_split_kernel(const float* __restrict__ cosT,
                                  const float* __restrict__ sinT)
{
    const int idx = blockIdx.x * blockDim.x + threadIdx.x;
    const int d   = idx & 31;
    const int t   = (idx >> 5) & (T - 1);
    const int bh  = (idx >> 16) & (BHn - 1);
    const int arr = idx >> 22;          // 0 = Q, 1 = K
    const float* P = arr ? g_Kf : g_Qf;
    __nv_bfloat16* Ph = arr ? g_Kh : g_Qh;
    __nv_bfloat16* Pl = arr ? g_Kl : g_Ql;
    const size_t base = ((size_t)bh * T + t) * DH;
    const float u1 = P[base + d], u2 = P[base + d + 32];
    const float c = cosT[t * DH + d], s = sinT[t * DH + d];
    float o1 = u1 * c - u2 * s;
    float o2 = u2 * c + u1 * s;
    if (arr == 0) { o1 *= 0.125f; o2 *= 0.125f; }
    __nv_bfloat16 h1 = __float2bfloat16_rn(o1), h2 = __float2bfloat16_rn(o2);
    Ph[base + d]      = h1;
    Pl[base + d]      = __float2bfloat16_rn(o1 - __bfloat162float(h1));
    Ph[base + d + 32] = h2;
    Pl[base + d + 32] = __float2bfloat16_rn(o2 - __bfloat162float(h2));
}

// ---------------------------------------------------------------------------
// Flash attention, split-bf16 HMMA. CTA = 128 thr (4 warps), 64 query rows;
// warp w owns rows 16w..16w+15 with Q frags in registers. K/V hi/lo tiles
// (64 keys x 64 d) cp.async double-buffered. S C-frag reused as P A-frag.
// ---------------------------------------------------------------------------
constexpr int FPITCH = 72;                    // halves/row
constexpr int FTILE  = 64 * FPITCH;
constexpr int FSTAGE = 4 * FTILE;             // Kh,Kl,Vh,Vl
constexpr int FSMEM  = 2 * FSTAGE * 2;        // 73728 bytes

__global__ __launch_bounds__(128, 1)
void flash_bf16()
{
    extern __shared__ __nv_bfloat16 fsm[];
    const int tid = threadIdx.x, lane = tid & 31, w = tid >> 5;
    const int g = lane >> 2, q = lane & 3;
    const int seg = lane >> 3, l7 = lane & 7;
    const int bh = blockIdx.y, q0 = blockIdx.x * 64;
    const size_t hb = (size_t)bh * T * DH;
    const unsigned sbase = (unsigned)__cvta_generic_to_shared(fsm);

    // Q fragments straight from gmem
    unsigned qh[4][4], ql[4][4];
    {
        const unsigned* Qh32 = (const unsigned*)(g_Qh + hb);
        const unsigned* Ql32 = (const unsigned*)(g_Ql + hb);
        const int r0 = q0 + w * 16 + g;
#pragma unroll
        for (int ks = 0; ks < 4; ks++) {
            const int c = ks * 8 + q;
            qh[ks][0] = Qh32[r0 * 32 + c];
            qh[ks][1] = Qh32[(r0 + 8) * 32 + c];
            qh[ks][2] = Qh32[r0 * 32 + c + 4];
            qh[ks][3] = Qh32[(r0 + 8) * 32 + c + 4];
            ql[ks][0] = Ql32[r0 * 32 + c];
            ql[ks][1] = Ql32[(r0 + 8) * 32 + c];
            ql[ks][2] = Ql32[r0 * 32 + c + 4];
            ql[ks][3] = Ql32[(r0 + 8) * 32 + c + 4];
        }
    }

    float oacc[8][4];
#pragma unroll
    for (int a = 0; a < 8; a++)
#pragma unroll
        for (int b = 0; b < 4; b++) oacc[a][b] = 0.f;
    float m_i[2] = {-1e30f, -1e30f}, l_i[2] = {0.f, 0.f};

    auto loadKV = [&](int stage, int n0) {
        unsigned sb = sbase + stage * FSTAGE * 2;
        const __nv_bfloat16* srcs[4] = {
            g_Kh + hb + (size_t)n0 * DH, g_Kl + hb + (size_t)n0 * DH,
            g_Vh + hb + (size_t)n0 * DH, g_Vl + hb + (size_t)n0 * DH };
#pragma unroll
        for (int a = 0; a < 4; a++)
#pragma unroll
            for (int i = 0; i < 4; i++) {
                int cid = tid + 128 * i;              // 0..511
                int r = cid >> 3, c = cid & 7;
                cp16(sb + (a * FTILE + r * FPITCH + c * 8) * 2, srcs[a] + r * 64 + c * 8);
            }
    };

    loadKV(0, 0);
    CP_COMMIT();
    for (int it = 0; it < T / 64; ++it) {
        if (it + 1 < T / 64) loadKV((it + 1) & 1, (it + 1) * 64);
        CP_COMMIT();
        CP_WAIT1();
        __syncthreads();
        unsigned sb = sbase + (it & 1) * FSTAGE * 2;
        unsigned kh = sb, kl = sb + FTILE * 2;
        unsigned vh = sb + 2 * FTILE * 2, vl = sb + 3 * FTILE * 2;

        // ---- S = Q @ K^T ----
        float sacc[8][4];
#pragma unroll
        for (int a = 0; a < 8; a++)
#pragma unroll
            for (int b = 0; b < 4; b++) sacc[a][b] = 0.f;
#pragma unroll
        for (int ks = 0; ks < 4; ks++) {
            const int kb = ks * 16;
#pragma unroll
            for (int np = 0; np < 4; np++) {
                // K as B-frag: non-trans ldsm; seg1 -> k+8, seg2 -> key+8
                const int nr = np * 16 + l7 + ((seg >> 1) & 1) * 8;
                const int kc = kb + (seg & 1) * 8;
                const unsigned off = (nr * FPITCH + kc) * 2;
                unsigned bkh[4], bkl[4];
                ldsm4(bkh, kh + off);
                ldsm4(bkl, kl + off);
                mma16816(sacc[2 * np],     qh[ks], bkh);
                mma16816(sacc[2 * np],     qh[ks], bkl);
                mma16816(sacc[2 * np],     ql[ks], bkh);
                mma16816(sacc[2 * np + 1], qh[ks], bkh + 2);
                mma16816(sacc[2 * np + 1], qh[ks], bkl + 2);
                mma16816(sacc[2 * np + 1], ql[ks], bkh + 2);
            }
        }

        // ---- online softmax (rows g, g+8; reduce across quad lanes) ----
#pragma unroll
        for (int r = 0; r < 2; r++) {
            float mx = -1e30f;
#pragma unroll
            for (int nt = 0; nt < 8; nt++)
                mx = fmaxf(mx, fmaxf(sacc[nt][2 * r], sacc[nt][2 * r + 1]));
            mx = fmaxf(mx, __shfl_xor_sync(0xffffffffu, mx, 1));
            mx = fmaxf(mx, __shfl_xor_sync(0xffffffffu, mx, 2));
            const float mnew = fmaxf(m_i[r], mx);
            const float corr = __expf(m_i[r] - mnew);
            m_i[r] = mnew;
            float rs = 0.f;
#pragma unroll
            for (int nt = 0; nt < 8; nt++) {
                sacc[nt][2 * r]     = __expf(sacc[nt][2 * r] - mnew);
                sacc[nt][2 * r + 1] = __expf(sacc[nt][2 * r + 1] - mnew);
                rs += sacc[nt][2 * r] + sacc[nt][2 * r + 1];
            }
            rs += __shfl_xor_sync(0xffffffffu, rs, 1);
            rs += __shfl_xor_sync(0xffffffffu, rs, 2);
            l_i[r] = l_i[r] * corr + rs;
#pragma unroll
            for (int nt = 0; nt < 8; nt++) {
                oacc[nt][2 * r]     *= corr;
                oacc[nt][2 * r + 1] *= corr;
            }
        }

        // ---- pack P hi/lo; S C-frag layout == PV A-frag layout ----
        unsigned ph[16], pl[16];
#pragma unroll
        for (int nt = 0; nt < 8; nt++)
#pragma unroll
            for (int hf = 0; hf < 2; hf++) {
                const float p0 = sacc[nt][2 * hf], p1 = sacc[nt][2 * hf + 1];
                const __nv_bfloat16 b0 = __float2bfloat16_rn(p0);
                const __nv_bfloat16 b1 = __float2bfloat16_rn(p1);
                __nv_bfloat162 hi2 = __halves2bfloat162(b0, b1);
                ph[nt * 2 + hf] = *reinterpret_cast<unsigned*>(&hi2);
                pl[nt * 2 + hf] = pack2f(p0 - __bfloat162float(b0), p1 - __bfloat162float(b1));
            }

        // ---- O += P @ V ----
#pragma unroll
        for (int ks = 0; ks < 4; ks++) {
            const unsigned* aP  = &ph[4 * ks];
            const unsigned* aPl = &pl[4 * ks];
#pragma unroll
            for (int np = 0; np < 4; np++) {
                // V as B-frag: trans ldsm; seg1 -> key+8, seg2 -> d+8
                const int vr = ks * 16 + l7 + (seg & 1) * 8;
                const int vc = np * 16 + ((seg >> 1) & 1) * 8;
                const unsigned off = (vr * FPITCH + vc) * 2;
                unsigned bvh[4], bvl[4];
                ldsm4t(bvh, vh + off);
                ldsm4t(bvl, vl + off);
                mma16816(oacc[2 * np],     aP,  bvh);
                mma16816(oacc[2 * np],     aP,  bvl);
                mma16816(oacc[2 * np],     aPl, bvh);
                mma16816(oacc[2 * np + 1], aP,  bvh + 2);
                mma16816(oacc[2 * np + 1], aP,  bvl + 2);
                mma16816(oacc[2 * np + 1], aPl, bvh + 2);
            }
        }
        __syncthreads();
    }

    // ---- epilogue: normalize, split, store pre-split AO for proj GEMM ----
    const int b = bh >> 4, h = bh & 15;
#pragma unroll
    for (int r = 0; r < 2; r++) {
        const float inv = 1.f / l_i[r];
        const int t = q0 + w * 16 + g + r * 8;
        const size_t base = ((size_t)(b * T + t)) * Dm + h * DH;
#pragma unroll
        for (int nt = 0; nt < 8; nt++) {
            const float v0 = oacc[nt][2 * r] * inv;
            const float v1 = oacc[nt][2 * r + 1] * inv;
            const __nv_bfloat16 h0 = __float2bfloat16_rn(v0);
            const __nv_bfloat16 h1 = __float2bfloat16_rn(v1);
            *reinterpret_cast<__nv_bfloat162*>(g_AOh + base + nt * 8 + 2 * q) =
                __halves2bfloat162(h0, h1);
            *reinterpret_cast<__nv_bfloat162*>(g_AOl + base + nt * 8 + 2 * q) =
                __floats2bfloat162_rn(v0 - __bfloat162float(h0), v1 - __bfloat162float(h1));
        }
    }
}

// ---------------------------------------------------------------------------
extern "C" void kernel_launch(void* const* d_in, const int* in_sizes, int n_in,
                              void* d_out, int out_size)
{
    (void)in_sizes; (void)n_in; (void)out_size;
    const float* x     = (const float*)d_in[0];
    const float* Wqkv  = (const float*)d_in[1];
    const float* bqkv  = (const float*)d_in[2];
    const float* Wproj = (const float*)d_in[3];
    const float* bproj = (const float*)d_in[4];
    const float* cosT  = (const float*)d_in[5];
    const float* sinT  = (const float*)d_in[6];
    float* out = (float*)d_out;

    cudaFuncSetAttribute(gemm_bf16<0>, cudaFuncAttributeMaxDynamicSharedMemorySize, GSMEM);
    cudaFuncSetAttribute(gemm_bf16<1>, cudaFuncAttributeMaxDynamicSharedMemorySize, GSMEM);
    cudaFuncSetAttribute(flash_bf16,   cudaFuncAttributeMaxDynamicSharedMemorySize, FSMEM);

    split4_kernel<0><<<(M * KD / 4 + 255) / 256, 256>>>((const float4*)x, M * KD / 4);
    split4_kernel<1><<<(KD * NQKV / 4 + 255) / 256, 256>>>((const float4*)Wqkv, KD * NQKV / 4);
    split4_kernel<2><<<(KD * Dm / 4 + 255) / 256, 256>>>((const float4*)Wproj, KD * Dm / 4);

    gemm_bf16<0><<<dim3(NQKV / 128, M / 128), 256, GSMEM>>>(bqkv, nullptr, NQKV);

    rope_split_kernel<<<(2 * BHn * T * 32) / 256, 256>>>(cosT, sinT);

    flash_bf16<<<dim3(T / 64, BHn), 128, FSMEM>>>();

    gemm_bf16<1><<<dim3(Dm / 128, M / 128), 256, GSMEM>>>(bproj, out, Dm);
}

// round 7
// speedup vs baseline: 2.8077x; 1.0876x over previous
#include <cuda_runtime.h>
#include <cuda_bf16.h>

// ---------------------------------------------------------------------------
// FlashMultiHeadAttention on tensor pipe: bf16 split-precision (hi+lo) HMMA.
// B=4, T=2048, D=1024, H=16, DH=64. Every matmul = 3x bf16 mma per k16 step.
// R7: force 2 CTAs/SM on GEMMs (regs<=128 via launch_bounds + per-mt A frags)
// and on flash.
// ---------------------------------------------------------------------------

constexpr int Bb  = 4;
constexpr int T   = 2048;
constexpr int Dm  = 1024;
constexpr int H   = 16;
constexpr int DH  = 64;
constexpr int BHn = Bb * H;       // 64
constexpr int M   = Bb * T;       // 8192
constexpr int KD  = Dm;           // 1024
constexpr int NQKV = 3 * Dm;      // 3072

// ---- scratch (__device__ statics; referenced only from device code) --------
__device__ __align__(256) __nv_bfloat16 g_xh[(size_t)M * KD],     g_xl[(size_t)M * KD];
__device__ __align__(256) __nv_bfloat16 g_w1h[(size_t)KD * NQKV], g_w1l[(size_t)KD * NQKV];
__device__ __align__(256) __nv_bfloat16 g_w2h[(size_t)KD * Dm],   g_w2l[(size_t)KD * Dm];
__device__ __align__(256) float         g_Qf[(size_t)BHn * T * DH], g_Kf[(size_t)BHn * T * DH];
__device__ __align__(256) __nv_bfloat16 g_Qh[(size_t)BHn * T * DH], g_Ql[(size_t)BHn * T * DH];
__device__ __align__(256) __nv_bfloat16 g_Kh[(size_t)BHn * T * DH], g_Kl[(size_t)BHn * T * DH];
__device__ __align__(256) __nv_bfloat16 g_Vh[(size_t)BHn * T * DH], g_Vl[(size_t)BHn * T * DH];
__device__ __align__(256) __nv_bfloat16 g_AOh[(size_t)M * Dm],      g_AOl[(size_t)M * Dm];

// ---- PTX helpers -----------------------------------------------------------
__device__ __forceinline__ void cp16(unsigned dst, const void* src) {
    asm volatile("cp.async.cg.shared.global [%0], [%1], 16;\n" :: "r"(dst), "l"(src));
}
#define CP_COMMIT()  asm volatile("cp.async.commit_group;\n" ::: "memory")
#define CP_WAIT1()   asm volatile("cp.async.wait_group 1;\n" ::: "memory")

__device__ __forceinline__ void ldsm4(unsigned* r, unsigned a) {
    asm volatile("ldmatrix.sync.aligned.m8n8.x4.shared.b16 {%0,%1,%2,%3}, [%4];\n"
                 : "=r"(r[0]), "=r"(r[1]), "=r"(r[2]), "=r"(r[3]) : "r"(a));
}
__device__ __forceinline__ void ldsm4t(unsigned* r, unsigned a) {
    asm volatile("ldmatrix.sync.aligned.m8n8.x4.trans.shared.b16 {%0,%1,%2,%3}, [%4];\n"
                 : "=r"(r[0]), "=r"(r[1]), "=r"(r[2]), "=r"(r[3]) : "r"(a));
}
__device__ __forceinline__ void mma16816(float* c, const unsigned* a, const unsigned* b) {
    asm volatile("mma.sync.aligned.m16n8k16.row.col.f32.bf16.bf16.f32 "
                 "{%0,%1,%2,%3}, {%4,%5,%6,%7}, {%8,%9}, {%0,%1,%2,%3};\n"
                 : "+f"(c[0]), "+f"(c[1]), "+f"(c[2]), "+f"(c[3])
                 : "r"(a[0]), "r"(a[1]), "r"(a[2]), "r"(a[3]), "r"(b[0]), "r"(b[1]));
}
__device__ __forceinline__ unsigned pack2f(float a, float b) {
    __nv_bfloat162 t = __floats2bfloat162_rn(a, b);
    return *reinterpret_cast<unsigned*>(&t);
}

// ---------------------------------------------------------------------------
// Elementwise fp32 -> (hi, lo) bf16 split. DST: 0 = x, 1 = Wqkv, 2 = Wproj.
// ---------------------------------------------------------------------------
template <int DST>
__global__ void split4_kernel(const float4* __restrict__ src, int n4)
{
    __nv_bfloat162* dh = reinterpret_cast<__nv_bfloat162*>(
        DST == 0 ? g_xh : DST == 1 ? g_w1h : g_w2h);
    __nv_bfloat162* dl = reinterpret_cast<__nv_bfloat162*>(
        DST == 0 ? g_xl : DST == 1 ? g_w1l : g_w2l);
    int i = blockIdx.x * blockDim.x + threadIdx.x;
    if (i >= n4) return;
    float4 v = src[i];
    __nv_bfloat16 h0 = __float2bfloat16_rn(v.x), h1 = __float2bfloat16_rn(v.y);
    __nv_bfloat16 h2 = __float2bfloat16_rn(v.z), h3 = __float2bfloat16_rn(v.w);
    dh[2 * i]     = __halves2bfloat162(h0, h1);
    dh[2 * i + 1] = __halves2bfloat162(h2, h3);
    dl[2 * i]     = __floats2bfloat162_rn(v.x - __bfloat162float(h0), v.y - __bfloat162float(h1));
    dl[2 * i + 1] = __floats2bfloat162_rn(v.z - __bfloat162float(h2), v.w - __bfloat162float(h3));
}

// ---------------------------------------------------------------------------
// GEMM: C[M,N] = A[M,1024] @ B[1024,N] + bias, split-bf16 HMMA.
// 128x128x32 tiles, 256 thr (8 warps 2x4), warp tile 64x32, cp.async 2-stage.
// 2 CTAs/SM (regs forced <=128; A frags loaded per-mt to shrink live set).
// ---------------------------------------------------------------------------
constexpr int APITCH = 40;    // halves/row
constexpr int BPITCH = 136;   // halves/row
constexpr int A_ELE  = 128 * APITCH;
constexpr int B_ELE  = 32 * BPITCH;
constexpr int GSTAGE = 2 * A_ELE + 2 * B_ELE;       // halves per stage
constexpr int GSMEM  = 2 * GSTAGE * 2;              // bytes (75776)

template <int MODE>
__global__ __launch_bounds__(256, 2)
void gemm_bf16(const float* __restrict__ bias, float* __restrict__ Cout, int N)
{
    const __nv_bfloat16* __restrict__ Ah = (MODE == 0) ? g_xh  : g_AOh;
    const __nv_bfloat16* __restrict__ Al = (MODE == 0) ? g_xl  : g_AOl;
    const __nv_bfloat16* __restrict__ Bh = (MODE == 0) ? g_w1h : g_w2h;
    const __nv_bfloat16* __restrict__ Bl = (MODE == 0) ? g_w1l : g_w2l;

    extern __shared__ __nv_bfloat16 gsm[];
    const int tid = threadIdx.x;
    const int m0 = blockIdx.y * 128, n0 = blockIdx.x * 128;
    const int wid = tid >> 5, lane = tid & 31;
    const int wm = wid >> 2, wn = wid & 3;
    const int g = lane >> 2, q = lane & 3;
    const int seg = lane >> 3, l7 = lane & 7;
    const unsigned sbase = (unsigned)__cvta_generic_to_shared(gsm);

    auto loadStage = [&](int stage, int k0) {
        unsigned sb = sbase + stage * GSTAGE * 2;
#pragma unroll
        for (int i = 0; i < 4; i++) {            // A: 1024 16B chunks
            int cid = tid + 256 * i;
            int prec = cid >> 9;
            int r = (cid & 511) >> 2, c = cid & 3;
            const __nv_bfloat16* src = (prec ? Al : Ah) + (size_t)(m0 + r) * KD + k0 + c * 8;
            cp16(sb + (prec * A_ELE + r * APITCH + c * 8) * 2, src);
        }
#pragma unroll
        for (int i = 0; i < 4; i++) {            // B: 1024 16B chunks
            int cid = tid + 256 * i;
            int prec = cid >> 9;
            int rr = (cid & 511) >> 4, cc = cid & 15;
            const __nv_bfloat16* src = (prec ? Bl : Bh) + (size_t)(k0 + rr) * N + n0 + cc * 8;
            cp16(sb + (2 * A_ELE + prec * B_ELE + rr * BPITCH + cc * 8) * 2, src);
        }
    };

    float acc[4][4][4];
#pragma unroll
    for (int a = 0; a < 4; a++)
#pragma unroll
        for (int b = 0; b < 4; b++)
#pragma unroll
            for (int c = 0; c < 4; c++) acc[a][b][c] = 0.f;

    loadStage(0, 0);
    CP_COMMIT();
    for (int it = 0; it < KD / 32; ++it) {
        if (it + 1 < KD / 32) loadStage((it + 1) & 1, (it + 1) * 32);
        CP_COMMIT();
        CP_WAIT1();
        __syncthreads();
        unsigned sb = sbase + (it & 1) * GSTAGE * 2;
        unsigned bB = sb + 2 * A_ELE * 2;
#pragma unroll
        for (int ks = 0; ks < 2; ks++) {
            const int kb = ks * 16;
            // B frags once per ks (16 regs live)
            unsigned bhf[2][4], blf[2][4];
#pragma unroll
            for (int np = 0; np < 2; np++) {
                int rr = kb + l7 + (seg & 1) * 8;
                int cc = wn * 32 + np * 16 + ((seg >> 1) & 1) * 8;
                unsigned bd = bB + (rr * BPITCH + cc) * 2;
                ldsm4t(bhf[np], bd);
                ldsm4t(blf[np], bd + B_ELE * 2);
            }
            // A frags per-mt (8 regs live) -> fits 128-reg budget, no spills
#pragma unroll
            for (int mt = 0; mt < 4; mt++) {
                int r2 = wm * 64 + mt * 16 + l7 + (seg & 1) * 8;
                int c2 = kb + ((seg >> 1) & 1) * 8;
                unsigned ad = sb + (r2 * APITCH + c2) * 2;
                unsigned ah[4], al[4];
                ldsm4(ah, ad);
                ldsm4(al, ad + A_ELE * 2);
#pragma unroll
                for (int nt = 0; nt < 4; nt++) {
                    const unsigned* b2h = &bhf[nt >> 1][(nt & 1) * 2];
                    const unsigned* b2l = &blf[nt >> 1][(nt & 1) * 2];
                    mma16816(acc[mt][nt], ah, b2h);   // hi*hi
                    mma16816(acc[mt][nt], ah, b2l);   // hi*lo
                    mma16816(acc[mt][nt], al, b2h);   // lo*hi
                }
            }
        }
        __syncthreads();
    }

#pragma unroll
    for (int mt = 0; mt < 4; mt++)
#pragma unroll
        for (int i = 0; i < 2; i++) {
            const int row = m0 + wm * 64 + mt * 16 + g + i * 8;
#pragma unroll
            for (int nt = 0; nt < 4; nt++)
#pragma unroll
                for (int j = 0; j < 2; j++) {
                    const int col = n0 + wn * 32 + nt * 8 + 2 * q + j;
                    const float v = acc[mt][nt][i * 2 + j] + bias[col];
                    if (MODE == 1) {
                        Cout[(size_t)row * N + col] = v;
                    } else {
                        const int sel = col >> 10;
                        const int rem = col & 1023;
                        const int hh = rem >> 6, dd = rem & 63;
                        const int b = row >> 11, t = row & 2047;
                        const size_t o = (((size_t)(b * H + hh)) * T + t) * DH + dd;
                        if (sel == 0)      g_Qf[o] = v;
                        else if (sel == 1) g_Kf[o] = v;
                        else {
                            __nv_bfloat16 h = __float2bfloat16_rn(v);
                            g_Vh[o] = h;
                            g_Vl[o] = __float2bfloat16_rn(v - __bfloat162float(h));
                        }
                    }
                }
        }
}

// ---------------------------------------------------------------------------
// RoPE on fp32 Q/K; outputs split bf16 hi/lo. Q pre-scaled by DH^-0.5.
// ---------------------------------------------------------------------------
__global__ void rope_split_kernel(const float* __restrict__ cosT,
                                  const float* __restrict__ sinT)
{
    const int idx = blockIdx.x * blockDim.x + threadIdx.x;
    const int d   = idx & 31;
    const int t   = (idx >> 5) & (T - 1);
    const int bh  = (idx >> 16) & (BHn - 1);
    const int arr = idx >> 22;          // 0 = Q, 1 = K
    const float* P = arr ? g_Kf : g_Qf;
    __nv_bfloat16* Ph = arr ? g_Kh : g_Qh;
    __nv_bfloat16* Pl = arr ? g_Kl : g_Ql;
    const size_t base = ((size_t)bh * T + t) * DH;
    const float u1 = P[base + d], u2 = P[base + d + 32];
    const float c = cosT[t * DH + d], s = sinT[t * DH + d];
    float o1 = u1 * c - u2 * s;
    float o2 = u2 * c + u1 * s;
    if (arr == 0) { o1 *= 0.125f; o2 *= 0.125f; }
    __nv_bfloat16 h1 = __float2bfloat16_rn(o1), h2 = __float2bfloat16_rn(o2);
    Ph[base + d]      = h1;
    Pl[base + d]      = __float2bfloat16_rn(o1 - __bfloat162float(h1));
    Ph[base + d + 32] = h2;
    Pl[base + d + 32] = __float2bfloat16_rn(o2 - __bfloat162float(h2));
}

// ---------------------------------------------------------------------------
// Flash attention, split-bf16 HMMA. CTA = 128 thr (4 warps), 64 query rows;
// warp w owns rows 16w..16w+15 with Q frags in registers. K/V hi/lo tiles
// (64 keys x 64 d) cp.async double-buffered. S C-frag reused as P A-frag.
// ---------------------------------------------------------------------------
constexpr int FPITCH = 72;                    // halves/row
constexpr int FTILE  = 64 * FPITCH;
constexpr int FSTAGE = 4 * FTILE;             // Kh,Kl,Vh,Vl
constexpr int FSMEM  = 2 * FSTAGE * 2;        // 73728 bytes

__global__ __launch_bounds__(128, 2)
void flash_bf16()
{
    extern __shared__ __nv_bfloat16 fsm[];
    const int tid = threadIdx.x, lane = tid & 31, w = tid >> 5;
    const int g = lane >> 2, q = lane & 3;
    const int seg = lane >> 3, l7 = lane & 7;
    const int bh = blockIdx.y, q0 = blockIdx.x * 64;
    const size_t hb = (size_t)bh * T * DH;
    const unsigned sbase = (unsigned)__cvta_generic_to_shared(fsm);

    // Q fragments straight from gmem
    unsigned qh[4][4], ql[4][4];
    {
        const unsigned* Qh32 = (const unsigned*)(g_Qh + hb);
        const unsigned* Ql32 = (const unsigned*)(g_Ql + hb);
        const int r0 = q0 + w * 16 + g;
#pragma unroll
        for (int ks = 0; ks < 4; ks++) {
            const int c = ks * 8 + q;
            qh[ks][0] = Qh32[r0 * 32 + c];
            qh[ks][1] = Qh32[(r0 + 8) * 32 + c];
            qh[ks][2] = Qh32[r0 * 32 + c + 4];
            qh[ks][3] = Qh32[(r0 + 8) * 32 + c + 4];
            ql[ks][0] = Ql32[r0 * 32 + c];
            ql[ks][1] = Ql32[(r0 + 8) * 32 + c];
            ql[ks][2] = Ql32[r0 * 32 + c + 4];
            ql[ks][3] = Ql32[(r0 + 8) * 32 + c + 4];
        }
    }

    float oacc[8][4];
#pragma unroll
    for (int a = 0; a < 8; a++)
#pragma unroll
        for (int b = 0; b < 4; b++) oacc[a][b] = 0.f;
    float m_i[2] = {-1e30f, -1e30f}, l_i[2] = {0.f, 0.f};

    auto loadKV = [&](int stage, int n0) {
        unsigned sb = sbase + stage * FSTAGE * 2;
        const __nv_bfloat16* srcs[4] = {
            g_Kh + hb + (size_t)n0 * DH, g_Kl + hb + (size_t)n0 * DH,
            g_Vh + hb + (size_t)n0 * DH, g_Vl + hb + (size_t)n0 * DH };
#pragma unroll
        for (int a = 0; a < 4; a++)
#pragma unroll
            for (int i = 0; i < 4; i++) {
                int cid = tid + 128 * i;              // 0..511
                int r = cid >> 3, c = cid & 7;
                cp16(sb + (a * FTILE + r * FPITCH + c * 8) * 2, srcs[a] + r * 64 + c * 8);
            }
    };

    loadKV(0, 0);
    CP_COMMIT();
    for (int it = 0; it < T / 64; ++it) {
        if (it + 1 < T / 64) loadKV((it + 1) & 1, (it + 1) * 64);
        CP_COMMIT();
        CP_WAIT1();
        __syncthreads();
        unsigned sb = sbase + (it & 1) * FSTAGE * 2;
        unsigned kh = sb, kl = sb + FTILE * 2;
        unsigned vh = sb + 2 * FTILE * 2, vl = sb + 3 * FTILE * 2;

        // ---- S = Q @ K^T ----
        float sacc[8][4];
#pragma unroll
        for (int a = 0; a < 8; a++)
#pragma unroll
            for (int b = 0; b < 4; b++) sacc[a][b] = 0.f;
#pragma unroll
        for (int ks = 0; ks < 4; ks++) {
            const int kb = ks * 16;
#pragma unroll
            for (int np = 0; np < 4; np++) {
                const int nr = np * 16 + l7 + ((seg >> 1) & 1) * 8;
                const int kc = kb + (seg & 1) * 8;
                const unsigned off = (nr * FPITCH + kc) * 2;
                unsigned bkh[4], bkl[4];
                ldsm4(bkh, kh + off);
                ldsm4(bkl, kl + off);
                mma16816(sacc[2 * np],     qh[ks], bkh);
                mma16816(sacc[2 * np],     qh[ks], bkl);
                mma16816(sacc[2 * np],     ql[ks], bkh);
                mma16816(sacc[2 * np + 1], qh[ks], bkh + 2);
                mma16816(sacc[2 * np + 1], qh[ks], bkl + 2);
                mma16816(sacc[2 * np + 1], ql[ks], bkh + 2);
            }
        }

        // ---- online softmax (rows g, g+8; reduce across quad lanes) ----
#pragma unroll
        for (int r = 0; r < 2; r++) {
            float mx = -1e30f;
#pragma unroll
            for (int nt = 0; nt < 8; nt++)
                mx = fmaxf(mx, fmaxf(sacc[nt][2 * r], sacc[nt][2 * r + 1]));
            mx = fmaxf(mx, __shfl_xor_sync(0xffffffffu, mx, 1));
            mx = fmaxf(mx, __shfl_xor_sync(0xffffffffu, mx, 2));
            const float mnew = fmaxf(m_i[r], mx);
            const float corr = __expf(m_i[r] - mnew);
            m_i[r] = mnew;
            float rs = 0.f;
#pragma unroll
            for (int nt = 0; nt < 8; nt++) {
                sacc[nt][2 * r]     = __expf(sacc[nt][2 * r] - mnew);
                sacc[nt][2 * r + 1] = __expf(sacc[nt][2 * r + 1] - mnew);
                rs += sacc[nt][2 * r] + sacc[nt][2 * r + 1];
            }
            rs += __shfl_xor_sync(0xffffffffu, rs, 1);
            rs += __shfl_xor_sync(0xffffffffu, rs, 2);
            l_i[r] = l_i[r] * corr + rs;
#pragma unroll
            for (int nt = 0; nt < 8; nt++) {
                oacc[nt][2 * r]     *= corr;
                oacc[nt][2 * r + 1] *= corr;
            }
        }

        // ---- pack P hi/lo; S C-frag layout == PV A-frag layout ----
        unsigned ph[16], pl[16];
#pragma unroll
        for (int nt = 0; nt < 8; nt++)
#pragma unroll
            for (int hf = 0; hf < 2; hf++) {
                const float p0 = sacc[nt][2 * hf], p1 = sacc[nt][2 * hf + 1];
                const __nv_bfloat16 b0 = __float2bfloat16_rn(p0);
                const __nv_bfloat16 b1 = __float2bfloat16_rn(p1);
                __nv_bfloat162 hi2 = __halves2bfloat162(b0, b1);
                ph[nt * 2 + hf] = *reinterpret_cast<unsigned*>(&hi2);
                pl[nt * 2 + hf] = pack2f(p0 - __bfloat162float(b0), p1 - __bfloat162float(b1));
            }

        // ---- O += P @ V ----
#pragma unroll
        for (int ks = 0; ks < 4; ks++) {
            const unsigned* aP  = &ph[4 * ks];
            const unsigned* aPl = &pl[4 * ks];
#pragma unroll
            for (int np = 0; np < 4; np++) {
                const int vr = ks * 16 + l7 + (seg & 1) * 8;
                const int vc = np * 16 + ((seg >> 1) & 1) * 8;
                const unsigned off = (vr * FPITCH + vc) * 2;
                unsigned bvh[4], bvl[4];
                ldsm4t(bvh, vh + off);
                ldsm4t(bvl, vl + off);
                mma16816(oacc[2 * np],     aP,  bvh);
                mma16816(oacc[2 * np],     aP,  bvl);
                mma16816(oacc[2 * np],     aPl, bvh);
                mma16816(oacc[2 * np + 1], aP,  bvh + 2);
                mma16816(oacc[2 * np + 1], aP,  bvl + 2);
                mma16816(oacc[2 * np + 1], aPl, bvh + 2);
            }
        }
        __syncthreads();
    }

    // ---- epilogue: normalize, split, store pre-split AO for proj GEMM ----
    const int b = bh >> 4, h = bh & 15;
#pragma unroll
    for (int r = 0; r < 2; r++) {
        const float inv = 1.f / l_i[r];
        const int t = q0 + w * 16 + g + r * 8;
        const size_t base = ((size_t)(b * T + t)) * Dm + h * DH;
#pragma unroll
        for (int nt = 0; nt < 8; nt++) {
            const float v0 = oacc[nt][2 * r] * inv;
            const float v1 = oacc[nt][2 * r + 1] * inv;
            const __nv_bfloat16 h0 = __float2bfloat16_rn(v0);
            const __nv_bfloat16 h1 = __float2bfloat16_rn(v1);
            *reinterpret_cast<__nv_bfloat162*>(g_AOh + base + nt * 8 + 2 * q) =
                __halves2bfloat162(h0, h1);
            *reinterpret_cast<__nv_bfloat162*>(g_AOl + base + nt * 8 + 2 * q) =
                __floats2bfloat162_rn(v0 - __bfloat162float(h0), v1 - __bfloat162float(h1));
        }
    }
}

// ---------------------------------------------------------------------------
extern "C" void kernel_launch(void* const* d_in, const int* in_sizes, int n_in,
                              void* d_out, int out_size)
{
    (void)in_sizes; (void)n_in; (void)out_size;
    const float* x     = (const float*)d_in[0];
    const float* Wqkv  = (const float*)d_in[1];
    const float* bqkv  = (const float*)d_in[2];
    const float* Wproj = (const float*)d_in[3];
    const float* bproj = (const float*)d_in[4];
    const float* cosT  = (const float*)d_in[5];
    const float* sinT  = (const float*)d_in[6];
    float* out = (float*)d_out;

    cudaFuncSetAttribute(gemm_bf16<0>, cudaFuncAttributeMaxDynamicSharedMemorySize, GSMEM);
    cudaFuncSetAttribute(gemm_bf16<1>, cudaFuncAttributeMaxDynamicSharedMemorySize, GSMEM);
    cudaFuncSetAttribute(flash_bf16,   cudaFuncAttributeMaxDynamicSharedMemorySize, FSMEM);

    split4_kernel<0><<<(M * KD / 4 + 255) / 256, 256>>>((const float4*)x, M * KD / 4);
    split4_kernel<1><<<(KD * NQKV / 4 + 255) / 256, 256>>>((const float4*)Wqkv, KD * NQKV / 4);
    split4_kernel<2><<<(KD * Dm / 4 + 255) / 256, 256>>>((const float4*)Wproj, KD * Dm / 4);

    gemm_bf16<0><<<dim3(NQKV / 128, M / 128), 256, GSMEM>>>(bqkv, nullptr, NQKV);

    rope_split_kernel<<<(2 * BHn * T * 32) / 256, 256>>>(cosT, sinT);

    flash_bf16<<<dim3(T / 64, BHn), 128, FSMEM>>>();

    gemm_bf16<1><<<dim3(Dm / 128, M / 128), 256, GSMEM>>>(bproj, out, Dm);
}

// round 8
// speedup vs baseline: 2.8153x; 1.0027x over previous
#include <cuda_runtime.h>
#include <cuda_bf16.h>

// ---------------------------------------------------------------------------
// FlashMultiHeadAttention on tensor pipe: bf16 split-precision (hi+lo) HMMA.
// R8: 3-stage cp.async pipelines with ONE __syncthreads per iteration;
// flash widened to 128 q-rows/CTA (halves K/V traffic).
// ---------------------------------------------------------------------------

constexpr int Bb  = 4;
constexpr int T   = 2048;
constexpr int Dm  = 1024;
constexpr int H   = 16;
constexpr int DH  = 64;
constexpr int BHn = Bb * H;       // 64
constexpr int M   = Bb * T;       // 8192
constexpr int KD  = Dm;           // 1024
constexpr int NQKV = 3 * Dm;      // 3072

// ---- scratch (__device__ statics; referenced only from device code) --------
__device__ __align__(256) __nv_bfloat16 g_xh[(size_t)M * KD],     g_xl[(size_t)M * KD];
__device__ __align__(256) __nv_bfloat16 g_w1h[(size_t)KD * NQKV], g_w1l[(size_t)KD * NQKV];
__device__ __align__(256) __nv_bfloat16 g_w2h[(size_t)KD * Dm],   g_w2l[(size_t)KD * Dm];
__device__ __align__(256) float         g_Qf[(size_t)BHn * T * DH], g_Kf[(size_t)BHn * T * DH];
__device__ __align__(256) __nv_bfloat16 g_Qh[(size_t)BHn * T * DH], g_Ql[(size_t)BHn * T * DH];
__device__ __align__(256) __nv_bfloat16 g_Kh[(size_t)BHn * T * DH], g_Kl[(size_t)BHn * T * DH];
__device__ __align__(256) __nv_bfloat16 g_Vh[(size_t)BHn * T * DH], g_Vl[(size_t)BHn * T * DH];
__device__ __align__(256) __nv_bfloat16 g_AOh[(size_t)M * Dm],      g_AOl[(size_t)M * Dm];

// ---- PTX helpers -----------------------------------------------------------
__device__ __forceinline__ void cp16(unsigned dst, const void* src) {
    asm volatile("cp.async.cg.shared.global [%0], [%1], 16;\n" :: "r"(dst), "l"(src));
}
#define CP_COMMIT()    asm volatile("cp.async.commit_group;\n" ::: "memory")
#define CP_WAIT_G1()   asm volatile("cp.async.wait_group 1;\n" ::: "memory")

__device__ __forceinline__ void ldsm4(unsigned* r, unsigned a) {
    asm volatile("ldmatrix.sync.aligned.m8n8.x4.shared.b16 {%0,%1,%2,%3}, [%4];\n"
                 : "=r"(r[0]), "=r"(r[1]), "=r"(r[2]), "=r"(r[3]) : "r"(a));
}
__device__ __forceinline__ void ldsm4t(unsigned* r, unsigned a) {
    asm volatile("ldmatrix.sync.aligned.m8n8.x4.trans.shared.b16 {%0,%1,%2,%3}, [%4];\n"
                 : "=r"(r[0]), "=r"(r[1]), "=r"(r[2]), "=r"(r[3]) : "r"(a));
}
__device__ __forceinline__ void mma16816(float* c, const unsigned* a, const unsigned* b) {
    asm volatile("mma.sync.aligned.m16n8k16.row.col.f32.bf16.bf16.f32 "
                 "{%0,%1,%2,%3}, {%4,%5,%6,%7}, {%8,%9}, {%0,%1,%2,%3};\n"
                 : "+f"(c[0]), "+f"(c[1]), "+f"(c[2]), "+f"(c[3])
                 : "r"(a[0]), "r"(a[1]), "r"(a[2]), "r"(a[3]), "r"(b[0]), "r"(b[1]));
}
__device__ __forceinline__ unsigned pack2f(float a, float b) {
    __nv_bfloat162 t = __floats2bfloat162_rn(a, b);
    return *reinterpret_cast<unsigned*>(&t);
}

// ---------------------------------------------------------------------------
// Elementwise fp32 -> (hi, lo) bf16 split. DST: 0 = x, 1 = Wqkv, 2 = Wproj.
// ---------------------------------------------------------------------------
template <int DST>
__global__ void split4_kernel(const float4* __restrict__ src, int n4)
{
    __nv_bfloat162* dh = reinterpret_cast<__nv_bfloat162*>(
        DST == 0 ? g_xh : DST == 1 ? g_w1h : g_w2h);
    __nv_bfloat162* dl = reinterpret_cast<__nv_bfloat162*>(
        DST == 0 ? g_xl : DST == 1 ? g_w1l : g_w2l);
    int i = blockIdx.x * blockDim.x + threadIdx.x;
    if (i >= n4) return;
    float4 v = src[i];
    __nv_bfloat16 h0 = __float2bfloat16_rn(v.x), h1 = __float2bfloat16_rn(v.y);
    __nv_bfloat16 h2 = __float2bfloat16_rn(v.z), h3 = __float2bfloat16_rn(v.w);
    dh[2 * i]     = __halves2bfloat162(h0, h1);
    dh[2 * i + 1] = __halves2bfloat162(h2, h3);
    dl[2 * i]     = __floats2bfloat162_rn(v.x - __bfloat162float(h0), v.y - __bfloat162float(h1));
    dl[2 * i + 1] = __floats2bfloat162_rn(v.z - __bfloat162float(h2), v.w - __bfloat162float(h3));
}

// ---------------------------------------------------------------------------
// GEMM: C[M,N] = A[M,1024] @ B[1024,N] + bias, split-bf16 HMMA.
// 128x128x32 tiles, 256 thr (8 warps 2x4), warp tile 64x32.
// 3-stage cp.async pipeline, ONE __syncthreads per k-iteration, 2 CTAs/SM.
// ---------------------------------------------------------------------------
constexpr int APITCH = 40;    // halves/row (8-row ldsm phases conflict-free)
constexpr int BPITCH = 136;   // halves/row
constexpr int A_ELE  = 128 * APITCH;
constexpr int B_ELE  = 32 * BPITCH;
constexpr int GSTAGE = 2 * A_ELE + 2 * B_ELE;       // halves per stage (18944)
constexpr int GSTAGES = 3;
constexpr int GSMEM  = GSTAGES * GSTAGE * 2;        // 113664 bytes

template <int MODE>
__global__ __launch_bounds__(256, 2)
void gemm_bf16(const float* __restrict__ bias, float* __restrict__ Cout, int N)
{
    const __nv_bfloat16* __restrict__ Ah = (MODE == 0) ? g_xh  : g_AOh;
    const __nv_bfloat16* __restrict__ Al = (MODE == 0) ? g_xl  : g_AOl;
    const __nv_bfloat16* __restrict__ Bh = (MODE == 0) ? g_w1h : g_w2h;
    const __nv_bfloat16* __restrict__ Bl = (MODE == 0) ? g_w1l : g_w2l;

    extern __shared__ __nv_bfloat16 gsm[];
    const int tid = threadIdx.x;
    const int m0 = blockIdx.y * 128, n0 = blockIdx.x * 128;
    const int wid = tid >> 5, lane = tid & 31;
    const int wm = wid >> 2, wn = wid & 3;
    const int g = lane >> 2, q = lane & 3;
    const int seg = lane >> 3, l7 = lane & 7;
    const unsigned sbase = (unsigned)__cvta_generic_to_shared(gsm);

    auto loadStage = [&](int stage, int k0) {
        unsigned sb = sbase + stage * GSTAGE * 2;
#pragma unroll
        for (int i = 0; i < 4; i++) {            // A: 1024 16B chunks
            int cid = tid + 256 * i;
            int prec = cid >> 9;
            int r = (cid & 511) >> 2, c = cid & 3;
            const __nv_bfloat16* src = (prec ? Al : Ah) + (size_t)(m0 + r) * KD + k0 + c * 8;
            cp16(sb + (prec * A_ELE + r * APITCH + c * 8) * 2, src);
        }
#pragma unroll
        for (int i = 0; i < 4; i++) {            // B: 1024 16B chunks
            int cid = tid + 256 * i;
            int prec = cid >> 9;
            int rr = (cid & 511) >> 4, cc = cid & 15;
            const __nv_bfloat16* src = (prec ? Bl : Bh) + (size_t)(k0 + rr) * N + n0 + cc * 8;
            cp16(sb + (2 * A_ELE + prec * B_ELE + rr * BPITCH + cc * 8) * 2, src);
        }
    };

    float acc[4][4][4];
#pragma unroll
    for (int a = 0; a < 4; a++)
#pragma unroll
        for (int b = 0; b < 4; b++)
#pragma unroll
            for (int c = 0; c < 4; c++) acc[a][b][c] = 0.f;

    constexpr int NIT = KD / 32;       // 32
    loadStage(0, 0);  CP_COMMIT();
    loadStage(1, 32); CP_COMMIT();

    for (int it = 0; it < NIT; ++it) {
        CP_WAIT_G1();                  // stage it%3 landed
        __syncthreads();               // all warps done computing stage (it+2)%3
        if (it + 2 < NIT) loadStage((it + 2) % 3, (it + 2) * 32);
        CP_COMMIT();

        unsigned sb = sbase + (it % 3) * GSTAGE * 2;
        unsigned bB = sb + 2 * A_ELE * 2;
#pragma unroll
        for (int ks = 0; ks < 2; ks++) {
            const int kb = ks * 16;
            unsigned bhf[2][4], blf[2][4];
#pragma unroll
            for (int np = 0; np < 2; np++) {
                int rr = kb + l7 + (seg & 1) * 8;
                int cc = wn * 32 + np * 16 + ((seg >> 1) & 1) * 8;
                unsigned bd = bB + (rr * BPITCH + cc) * 2;
                ldsm4t(bhf[np], bd);
                ldsm4t(blf[np], bd + B_ELE * 2);
            }
#pragma unroll
            for (int mt = 0; mt < 4; mt++) {
                int r2 = wm * 64 + mt * 16 + l7 + (seg & 1) * 8;
                int c2 = kb + ((seg >> 1) & 1) * 8;
                unsigned ad = sb + (r2 * APITCH + c2) * 2;
                unsigned ah[4], al[4];
                ldsm4(ah, ad);
                ldsm4(al, ad + A_ELE * 2);
#pragma unroll
                for (int nt = 0; nt < 4; nt++) {
                    const unsigned* b2h = &bhf[nt >> 1][(nt & 1) * 2];
                    const unsigned* b2l = &blf[nt >> 1][(nt & 1) * 2];
                    mma16816(acc[mt][nt], ah, b2h);   // hi*hi
                    mma16816(acc[mt][nt], ah, b2l);   // hi*lo
                    mma16816(acc[mt][nt], al, b2h);   // lo*hi
                }
            }
        }
    }

#pragma unroll
    for (int mt = 0; mt < 4; mt++)
#pragma unroll
        for (int i = 0; i < 2; i++) {
            const int row = m0 + wm * 64 + mt * 16 + g + i * 8;
#pragma unroll
            for (int nt = 0; nt < 4; nt++)
#pragma unroll
                for (int j = 0; j < 2; j++) {
                    const int col = n0 + wn * 32 + nt * 8 + 2 * q + j;
                    const float v = acc[mt][nt][i * 2 + j] + bias[col];
                    if (MODE == 1) {
                        Cout[(size_t)row * N + col] = v;
                    } else {
                        const int sel = col >> 10;
                        const int rem = col & 1023;
                        const int hh = rem >> 6, dd = rem & 63;
                        const int b = row >> 11, t = row & 2047;
                        const size_t o = (((size_t)(b * H + hh)) * T + t) * DH + dd;
                        if (sel == 0)      g_Qf[o] = v;
                        else if (sel == 1) g_Kf[o] = v;
                        else {
                            __nv_bfloat16 h = __float2bfloat16_rn(v);
                            g_Vh[o] = h;
                            g_Vl[o] = __float2bfloat16_rn(v - __bfloat162float(h));
                        }
                    }
                }
        }
}

// ---------------------------------------------------------------------------
// RoPE on fp32 Q/K; outputs split bf16 hi/lo. Q pre-scaled by DH^-0.5.
// ---------------------------------------------------------------------------
__global__ void rope_split_kernel(const float* __restrict__ cosT,
                                  const float* __restrict__ sinT)
{
    const int idx = blockIdx.x * blockDim.x + threadIdx.x;
    const int d   = idx & 31;
    const int t   = (idx >> 5) & (T - 1);
    const int bh  = (idx >> 16) & (BHn - 1);
    const int arr = idx >> 22;          // 0 = Q, 1 = K
    const float* P = arr ? g_Kf : g_Qf;
    __nv_bfloat16* Ph = arr ? g_Kh : g_Qh;
    __nv_bfloat16* Pl = arr ? g_Kl : g_Ql;
    const size_t base = ((size_t)bh * T + t) * DH;
    const float u1 = P[base + d], u2 = P[base + d + 32];
    const float c = cosT[t * DH + d], s = sinT[t * DH + d];
    float o1 = u1 * c - u2 * s;
    float o2 = u2 * c + u1 * s;
    if (arr == 0) { o1 *= 0.125f; o2 *= 0.125f; }
    __nv_bfloat16 h1 = __float2bfloat16_rn(o1), h2 = __float2bfloat16_rn(o2);
    Ph[base + d]      = h1;
    Pl[base + d]      = __float2bfloat16_rn(o1 - __bfloat162float(h1));
    Ph[base + d + 32] = h2;
    Pl[base + d + 32] = __float2bfloat16_rn(o2 - __bfloat162float(h2));
}

// ---------------------------------------------------------------------------
// Flash attention, split-bf16 HMMA. CTA = 256 thr (8 warps), 128 query rows;
// warp w owns rows 16w..16w+15 (Q frags in registers). K/V hi/lo tiles
// (64 keys x 64 d) in a 3-stage cp.async pipeline, one sync per tile.
// S C-frag reused directly as P A-frag.
// ---------------------------------------------------------------------------
constexpr int FPITCH = 72;                    // halves/row
constexpr int FTILE  = 64 * FPITCH;
constexpr int FSTAGE = 4 * FTILE;             // Kh,Kl,Vh,Vl (36864 B)
constexpr int FSTAGES = 3;
constexpr int FSMEM  = FSTAGES * FSTAGE * 2;  // 110592 bytes

__global__ __launch_bounds__(256, 1)
void flash_bf16()
{
    extern __shared__ __nv_bfloat16 fsm[];
    const int tid = threadIdx.x, lane = tid & 31, w = tid >> 5;
    const int g = lane >> 2, q = lane & 3;
    const int seg = lane >> 3, l7 = lane & 7;
    const int bh = blockIdx.y, q0 = blockIdx.x * 128;
    const size_t hb = (size_t)bh * T * DH;
    const unsigned sbase = (unsigned)__cvta_generic_to_shared(fsm);

    // Q fragments straight from gmem
    unsigned qh[4][4], ql[4][4];
    {
        const unsigned* Qh32 = (const unsigned*)(g_Qh + hb);
        const unsigned* Ql32 = (const unsigned*)(g_Ql + hb);
        const int r0 = q0 + w * 16 + g;
#pragma unroll
        for (int ks = 0; ks < 4; ks++) {
            const int c = ks * 8 + q;
            qh[ks][0] = Qh32[r0 * 32 + c];
            qh[ks][1] = Qh32[(r0 + 8) * 32 + c];
            qh[ks][2] = Qh32[r0 * 32 + c + 4];
            qh[ks][3] = Qh32[(r0 + 8) * 32 + c + 4];
            ql[ks][0] = Ql32[r0 * 32 + c];
            ql[ks][1] = Ql32[(r0 + 8) * 32 + c];
            ql[ks][2] = Ql32[r0 * 32 + c + 4];
            ql[ks][3] = Ql32[(r0 + 8) * 32 + c + 4];
        }
    }

    float oacc[8][4];
#pragma unroll
    for (int a = 0; a < 8; a++)
#pragma unroll
        for (int b = 0; b < 4; b++) oacc[a][b] = 0.f;
    float m_i[2] = {-1e30f, -1e30f}, l_i[2] = {0.f, 0.f};

    auto loadKV = [&](int stage, int n0) {
        unsigned sb = sbase + stage * FSTAGE * 2;
        const __nv_bfloat16* srcs[4] = {
            g_Kh + hb + (size_t)n0 * DH, g_Kl + hb + (size_t)n0 * DH,
            g_Vh + hb + (size_t)n0 * DH, g_Vl + hb + (size_t)n0 * DH };
#pragma unroll
        for (int a = 0; a < 4; a++)
#pragma unroll
            for (int i = 0; i < 2; i++) {
                int cid = tid + 256 * i;              // 0..511
                int r = cid >> 3, c = cid & 7;
                cp16(sb + (a * FTILE + r * FPITCH + c * 8) * 2, srcs[a] + r * 64 + c * 8);
            }
    };

    constexpr int NIT = T / 64;        // 32
    loadKV(0, 0);  CP_COMMIT();
    loadKV(1, 64); CP_COMMIT();

    for (int it = 0; it < NIT; ++it) {
        CP_WAIT_G1();                  // stage it%3 landed
        __syncthreads();               // all warps done with stage (it+2)%3
        if (it + 2 < NIT) loadKV((it + 2) % 3, (it + 2) * 64);
        CP_COMMIT();

        unsigned sb = sbase + (it % 3) * FSTAGE * 2;
        unsigned kh = sb, kl = sb + FTILE * 2;
        unsigned vh = sb + 2 * FTILE * 2, vl = sb + 3 * FTILE * 2;

        // ---- S = Q @ K^T ----
        float sacc[8][4];
#pragma unroll
        for (int a = 0; a < 8; a++)
#pragma unroll
            for (int b = 0; b < 4; b++) sacc[a][b] = 0.f;
#pragma unroll
        for (int ks = 0; ks < 4; ks++) {
            const int kb = ks * 16;
#pragma unroll
            for (int np = 0; np < 4; np++) {
                const int nr = np * 16 + l7 + ((seg >> 1) & 1) * 8;
                const int kc = kb + (seg & 1) * 8;
                const unsigned off = (nr * FPITCH + kc) * 2;
                unsigned bkh[4], bkl[4];
                ldsm4(bkh, kh + off);
                ldsm4(bkl, kl + off);
                mma16816(sacc[2 * np],     qh[ks], bkh);
                mma16816(sacc[2 * np],     qh[ks], bkl);
                mma16816(sacc[2 * np],     ql[ks], bkh);
                mma16816(sacc[2 * np + 1], qh[ks], bkh + 2);
                mma16816(sacc[2 * np + 1], qh[ks], bkl + 2);
                mma16816(sacc[2 * np + 1], ql[ks], bkh + 2);
            }
        }

        // ---- online softmax (rows g, g+8; reduce across quad lanes) ----
#pragma unroll
        for (int r = 0; r < 2; r++) {
            float mx = -1e30f;
#pragma unroll
            for (int nt = 0; nt < 8; nt++)
                mx = fmaxf(mx, fmaxf(sacc[nt][2 * r], sacc[nt][2 * r + 1]));
            mx = fmaxf(mx, __shfl_xor_sync(0xffffffffu, mx, 1));
            mx = fmaxf(mx, __shfl_xor_sync(0xffffffffu, mx, 2));
            const float mnew = fmaxf(m_i[r], mx);
            const float corr = __expf(m_i[r] - mnew);
            m_i[r] = mnew;
            float rs = 0.f;
#pragma unroll
            for (int nt = 0; nt < 8; nt++) {
                sacc[nt][2 * r]     = __expf(sacc[nt][2 * r] - mnew);
                sacc[nt][2 * r + 1] = __expf(sacc[nt][2 * r + 1] - mnew);
                rs += sacc[nt][2 * r] + sacc[nt][2 * r + 1];
            }
            rs += __shfl_xor_sync(0xffffffffu, rs, 1);
            rs += __shfl_xor_sync(0xffffffffu, rs, 2);
            l_i[r] = l_i[r] * corr + rs;
#pragma unroll
            for (int nt = 0; nt < 8; nt++) {
                oacc[nt][2 * r]     *= corr;
                oacc[nt][2 * r + 1] *= corr;
            }
        }

        // ---- pack P hi/lo; S C-frag layout == PV A-frag layout ----
        unsigned ph[16], pl[16];
#pragma unroll
        for (int nt = 0; nt < 8; nt++)
#pragma unroll
            for (int hf = 0; hf < 2; hf++) {
                const float p0 = sacc[nt][2 * hf], p1 = sacc[nt][2 * hf + 1];
                const __nv_bfloat16 b0 = __float2bfloat16_rn(p0);
                const __nv_bfloat16 b1 = __float2bfloat16_rn(p1);
                __nv_bfloat162 hi2 = __halves2bfloat162(b0, b1);
                ph[nt * 2 + hf] = *reinterpret_cast<unsigned*>(&hi2);
                pl[nt * 2 + hf] = pack2f(p0 - __bfloat162float(b0), p1 - __bfloat162float(b1));
            }

        // ---- O += P @ V ----
#pragma unroll
        for (int ks = 0; ks < 4; ks++) {
            const unsigned* aP  = &ph[4 * ks];
            const unsigned* aPl = &pl[4 * ks];
#pragma unroll
            for (int np = 0; np < 4; np++) {
                const int vr = ks * 16 + l7 + (seg & 1) * 8;
                const int vc = np * 16 + ((seg >> 1) & 1) * 8;
                const unsigned off = (vr * FPITCH + vc) * 2;
                unsigned bvh[4], bvl[4];
                ldsm4t(bvh, vh + off);
                ldsm4t(bvl, vl + off);
                mma16816(oacc[2 * np],     aP,  bvh);
                mma16816(oacc[2 * np],     aP,  bvl);
                mma16816(oacc[2 * np],     aPl, bvh);
                mma16816(oacc[2 * np + 1], aP,  bvh + 2);
                mma16816(oacc[2 * np + 1], aP,  bvl + 2);
                mma16816(oacc[2 * np + 1], aPl, bvh + 2);
            }
        }
    }

    // ---- epilogue: normalize, split, store pre-split AO for proj GEMM ----
    const int b = bh >> 4, h = bh & 15;
#pragma unroll
    for (int r = 0; r < 2; r++) {
        const float inv = 1.f / l_i[r];
        const int t = q0 + w * 16 + g + r * 8;
        const size_t base = ((size_t)(b * T + t)) * Dm + h * DH;
#pragma unroll
        for (int nt = 0; nt < 8; nt++) {
            const float v0 = oacc[nt][2 * r] * inv;
            const float v1 = oacc[nt][2 * r + 1] * inv;
            const __nv_bfloat16 h0 = __float2bfloat16_rn(v0);
            const __nv_bfloat16 h1 = __float2bfloat16_rn(v1);
            *reinterpret_cast<__nv_bfloat162*>(g_AOh + base + nt * 8 + 2 * q) =
                __halves2bfloat162(h0, h1);
            *reinterpret_cast<__nv_bfloat162*>(g_AOl + base + nt * 8 + 2 * q) =
                __floats2bfloat162_rn(v0 - __bfloat162float(h0), v1 - __bfloat162float(h1));
        }
    }
}

// ---------------------------------------------------------------------------
extern "C" void kernel_launch(void* const* d_in, const int* in_sizes, int n_in,
                              void* d_out, int out_size)
{
    (void)in_sizes; (void)n_in; (void)out_size;
    const float* x     = (const float*)d_in[0];
    const float* Wqkv  = (const float*)d_in[1];
    const float* bqkv  = (const float*)d_in[2];
    const float* Wproj = (const float*)d_in[3];
    const float* bproj = (const float*)d_in[4];
    const float* cosT  = (const float*)d_in[5];
    const float* sinT  = (const float*)d_in[6];
    float* out = (float*)d_out;

    cudaFuncSetAttribute(gemm_bf16<0>, cudaFuncAttributeMaxDynamicSharedMemorySize, GSMEM);
    cudaFuncSetAttribute(gemm_bf16<1>, cudaFuncAttributeMaxDynamicSharedMemorySize, GSMEM);
    cudaFuncSetAttribute(flash_bf16,   cudaFuncAttributeMaxDynamicSharedMemorySize, FSMEM);

    split4_kernel<0><<<(M * KD / 4 + 255) / 256, 256>>>((const float4*)x, M * KD / 4);
    split4_kernel<1><<<(KD * NQKV / 4 + 255) / 256, 256>>>((const float4*)Wqkv, KD * NQKV / 4);
    split4_kernel<2><<<(KD * Dm / 4 + 255) / 256, 256>>>((const float4*)Wproj, KD * Dm / 4);

    gemm_bf16<0><<<dim3(NQKV / 128, M / 128), 256, GSMEM>>>(bqkv, nullptr, NQKV);

    rope_split_kernel<<<(2 * BHn * T * 32) / 256, 256>>>(cosT, sinT);

    flash_bf16<<<dim3(T / 128, BHn), 256, FSMEM>>>();

    gemm_bf16<1><<<dim3(Dm / 128, M / 128), 256, GSMEM>>>(bproj, out, Dm);
}

// round 9
// speedup vs baseline: 2.8257x; 1.0037x over previous
#include <cuda_runtime.h>
#include <cuda_bf16.h>

// ---------------------------------------------------------------------------
// FlashMultiHeadAttention on tensor pipe: bf16 split-precision (hi+lo) HMMA.
// R9: break accumulator RAW chains — consecutive MMAs always target different
// accumulators (term-major interleave). Summation order per-acc unchanged.
// ---------------------------------------------------------------------------

constexpr int Bb  = 4;
constexpr int T   = 2048;
constexpr int Dm  = 1024;
constexpr int H   = 16;
constexpr int DH  = 64;
constexpr int BHn = Bb * H;       // 64
constexpr int M   = Bb * T;       // 8192
constexpr int KD  = Dm;           // 1024
constexpr int NQKV = 3 * Dm;      // 3072

// ---- scratch (__device__ statics; referenced only from device code) --------
__device__ __align__(256) __nv_bfloat16 g_xh[(size_t)M * KD],     g_xl[(size_t)M * KD];
__device__ __align__(256) __nv_bfloat16 g_w1h[(size_t)KD * NQKV], g_w1l[(size_t)KD * NQKV];
__device__ __align__(256) __nv_bfloat16 g_w2h[(size_t)KD * Dm],   g_w2l[(size_t)KD * Dm];
__device__ __align__(256) float         g_Qf[(size_t)BHn * T * DH], g_Kf[(size_t)BHn * T * DH];
__device__ __align__(256) __nv_bfloat16 g_Qh[(size_t)BHn * T * DH], g_Ql[(size_t)BHn * T * DH];
__device__ __align__(256) __nv_bfloat16 g_Kh[(size_t)BHn * T * DH], g_Kl[(size_t)BHn * T * DH];
__device__ __align__(256) __nv_bfloat16 g_Vh[(size_t)BHn * T * DH], g_Vl[(size_t)BHn * T * DH];
__device__ __align__(256) __nv_bfloat16 g_AOh[(size_t)M * Dm],      g_AOl[(size_t)M * Dm];

// ---- PTX helpers -----------------------------------------------------------
__device__ __forceinline__ void cp16(unsigned dst, const void* src) {
    asm volatile("cp.async.cg.shared.global [%0], [%1], 16;\n" :: "r"(dst), "l"(src));
}
#define CP_COMMIT()    asm volatile("cp.async.commit_group;\n" ::: "memory")
#define CP_WAIT_G1()   asm volatile("cp.async.wait_group 1;\n" ::: "memory")

__device__ __forceinline__ void ldsm4(unsigned* r, unsigned a) {
    asm volatile("ldmatrix.sync.aligned.m8n8.x4.shared.b16 {%0,%1,%2,%3}, [%4];\n"
                 : "=r"(r[0]), "=r"(r[1]), "=r"(r[2]), "=r"(r[3]) : "r"(a));
}
__device__ __forceinline__ void ldsm4t(unsigned* r, unsigned a) {
    asm volatile("ldmatrix.sync.aligned.m8n8.x4.trans.shared.b16 {%0,%1,%2,%3}, [%4];\n"
                 : "=r"(r[0]), "=r"(r[1]), "=r"(r[2]), "=r"(r[3]) : "r"(a));
}
__device__ __forceinline__ void mma16816(float* c, const unsigned* a, const unsigned* b) {
    asm volatile("mma.sync.aligned.m16n8k16.row.col.f32.bf16.bf16.f32 "
                 "{%0,%1,%2,%3}, {%4,%5,%6,%7}, {%8,%9}, {%0,%1,%2,%3};\n"
                 : "+f"(c[0]), "+f"(c[1]), "+f"(c[2]), "+f"(c[3])
                 : "r"(a[0]), "r"(a[1]), "r"(a[2]), "r"(a[3]), "r"(b[0]), "r"(b[1]));
}
__device__ __forceinline__ unsigned pack2f(float a, float b) {
    __nv_bfloat162 t = __floats2bfloat162_rn(a, b);
    return *reinterpret_cast<unsigned*>(&t);
}

// ---------------------------------------------------------------------------
// Elementwise fp32 -> (hi, lo) bf16 split. DST: 0 = x, 1 = Wqkv, 2 = Wproj.
// ---------------------------------------------------------------------------
template <int DST>
__global__ void split4_kernel(const float4* __restrict__ src, int n4)
{
    __nv_bfloat162* dh = reinterpret_cast<__nv_bfloat162*>(
        DST == 0 ? g_xh : DST == 1 ? g_w1h : g_w2h);
    __nv_bfloat162* dl = reinterpret_cast<__nv_bfloat162*>(
        DST == 0 ? g_xl : DST == 1 ? g_w1l : g_w2l);
    int i = blockIdx.x * blockDim.x + threadIdx.x;
    if (i >= n4) return;
    float4 v = src[i];
    __nv_bfloat16 h0 = __float2bfloat16_rn(v.x), h1 = __float2bfloat16_rn(v.y);
    __nv_bfloat16 h2 = __float2bfloat16_rn(v.z), h3 = __float2bfloat16_rn(v.w);
    dh[2 * i]     = __halves2bfloat162(h0, h1);
    dh[2 * i + 1] = __halves2bfloat162(h2, h3);
    dl[2 * i]     = __floats2bfloat162_rn(v.x - __bfloat162float(h0), v.y - __bfloat162float(h1));
    dl[2 * i + 1] = __floats2bfloat162_rn(v.z - __bfloat162float(h2), v.w - __bfloat162float(h3));
}

// ---------------------------------------------------------------------------
// GEMM: C[M,N] = A[M,1024] @ B[1024,N] + bias, split-bf16 HMMA.
// 128x128x32 tiles, 256 thr (8 warps 2x4), warp tile 64x32.
// 3-stage cp.async pipeline, one sync/iter, 2 CTAs/SM.
// Inner loop: term-major MMA interleave (4-MMA spacing per accumulator).
// ---------------------------------------------------------------------------
constexpr int APITCH = 40;    // halves/row
constexpr int BPITCH = 136;   // halves/row
constexpr int A_ELE  = 128 * APITCH;
constexpr int B_ELE  = 32 * BPITCH;
constexpr int GSTAGE = 2 * A_ELE + 2 * B_ELE;       // halves per stage
constexpr int GSTAGES = 3;
constexpr int GSMEM  = GSTAGES * GSTAGE * 2;        // 113664 bytes

template <int MODE>
__global__ __launch_bounds__(256, 2)
void gemm_bf16(const float* __restrict__ bias, float* __restrict__ Cout, int N)
{
    const __nv_bfloat16* __restrict__ Ah = (MODE == 0) ? g_xh  : g_AOh;
    const __nv_bfloat16* __restrict__ Al = (MODE == 0) ? g_xl  : g_AOl;
    const __nv_bfloat16* __restrict__ Bh = (MODE == 0) ? g_w1h : g_w2h;
    const __nv_bfloat16* __restrict__ Bl = (MODE == 0) ? g_w1l : g_w2l;

    extern __shared__ __nv_bfloat16 gsm[];
    const int tid = threadIdx.x;
    const int m0 = blockIdx.y * 128, n0 = blockIdx.x * 128;
    const int wid = tid >> 5, lane = tid & 31;
    const int wm = wid >> 2, wn = wid & 3;
    const int g = lane >> 2, q = lane & 3;
    const int seg = lane >> 3, l7 = lane & 7;
    const unsigned sbase = (unsigned)__cvta_generic_to_shared(gsm);

    auto loadStage = [&](int stage, int k0) {
        unsigned sb = sbase + stage * GSTAGE * 2;
#pragma unroll
        for (int i = 0; i < 4; i++) {            // A: 1024 16B chunks
            int cid = tid + 256 * i;
            int prec = cid >> 9;
            int r = (cid & 511) >> 2, c = cid & 3;
            const __nv_bfloat16* src = (prec ? Al : Ah) + (size_t)(m0 + r) * KD + k0 + c * 8;
            cp16(sb + (prec * A_ELE + r * APITCH + c * 8) * 2, src);
        }
#pragma unroll
        for (int i = 0; i < 4; i++) {            // B: 1024 16B chunks
            int cid = tid + 256 * i;
            int prec = cid >> 9;
            int rr = (cid & 511) >> 4, cc = cid & 15;
            const __nv_bfloat16* src = (prec ? Bl : Bh) + (size_t)(k0 + rr) * N + n0 + cc * 8;
            cp16(sb + (2 * A_ELE + prec * B_ELE + rr * BPITCH + cc * 8) * 2, src);
        }
    };

    float acc[4][4][4];
#pragma unroll
    for (int a = 0; a < 4; a++)
#pragma unroll
        for (int b = 0; b < 4; b++)
#pragma unroll
            for (int c = 0; c < 4; c++) acc[a][b][c] = 0.f;

    constexpr int NIT = KD / 32;       // 32
    loadStage(0, 0);  CP_COMMIT();
    loadStage(1, 32); CP_COMMIT();

    for (int it = 0; it < NIT; ++it) {
        CP_WAIT_G1();
        __syncthreads();
        if (it + 2 < NIT) loadStage((it + 2) % 3, (it + 2) * 32);
        CP_COMMIT();

        unsigned sb = sbase + (it % 3) * GSTAGE * 2;
        unsigned bB = sb + 2 * A_ELE * 2;
#pragma unroll
        for (int ks = 0; ks < 2; ks++) {
            const int kb = ks * 16;
            unsigned bhf[2][4], blf[2][4];
#pragma unroll
            for (int np = 0; np < 2; np++) {
                int rr = kb + l7 + (seg & 1) * 8;
                int cc = wn * 32 + np * 16 + ((seg >> 1) & 1) * 8;
                unsigned bd = bB + (rr * BPITCH + cc) * 2;
                ldsm4t(bhf[np], bd);
                ldsm4t(blf[np], bd + B_ELE * 2);
            }
#pragma unroll
            for (int mt = 0; mt < 4; mt++) {
                int r2 = wm * 64 + mt * 16 + l7 + (seg & 1) * 8;
                int c2 = kb + ((seg >> 1) & 1) * 8;
                unsigned ad = sb + (r2 * APITCH + c2) * 2;
                unsigned ah[4], al[4];
                ldsm4(ah, ad);
                ldsm4(al, ad + A_ELE * 2);
                // term-major: consecutive MMAs hit different accumulators
#pragma unroll
                for (int nt = 0; nt < 4; nt++)      // hi*hi
                    mma16816(acc[mt][nt], ah, &bhf[nt >> 1][(nt & 1) * 2]);
#pragma unroll
                for (int nt = 0; nt < 4; nt++)      // hi*lo
                    mma16816(acc[mt][nt], ah, &blf[nt >> 1][(nt & 1) * 2]);
#pragma unroll
                for (int nt = 0; nt < 4; nt++)      // lo*hi
                    mma16816(acc[mt][nt], al, &bhf[nt >> 1][(nt & 1) * 2]);
            }
        }
    }

#pragma unroll
    for (int mt = 0; mt < 4; mt++)
#pragma unroll
        for (int i = 0; i < 2; i++) {
            const int row = m0 + wm * 64 + mt * 16 + g + i * 8;
#pragma unroll
            for (int nt = 0; nt < 4; nt++)
#pragma unroll
                for (int j = 0; j < 2; j++) {
                    const int col = n0 + wn * 32 + nt * 8 + 2 * q + j;
                    const float v = acc[mt][nt][i * 2 + j] + bias[col];
                    if (MODE == 1) {
                        Cout[(size_t)row * N + col] = v;
                    } else {
                        const int sel = col >> 10;
                        const int rem = col & 1023;
                        const int hh = rem >> 6, dd = rem & 63;
                        const int b = row >> 11, t = row & 2047;
                        const size_t o = (((size_t)(b * H + hh)) * T + t) * DH + dd;
                        if (sel == 0)      g_Qf[o] = v;
                        else if (sel == 1) g_Kf[o] = v;
                        else {
                            __nv_bfloat16 h = __float2bfloat16_rn(v);
                            g_Vh[o] = h;
                            g_Vl[o] = __float2bfloat16_rn(v - __bfloat162float(h));
                        }
                    }
                }
        }
}

// ---------------------------------------------------------------------------
// RoPE on fp32 Q/K; outputs split bf16 hi/lo. Q pre-scaled by DH^-0.5.
// ---------------------------------------------------------------------------
__global__ void rope_split_kernel(const float* __restrict__ cosT,
                                  const float* __restrict__ sinT)
{
    const int idx = blockIdx.x * blockDim.x + threadIdx.x;
    const int d   = idx & 31;
    const int t   = (idx >> 5) & (T - 1);
    const int bh  = (idx >> 16) & (BHn - 1);
    const int arr = idx >> 22;          // 0 = Q, 1 = K
    const float* P = arr ? g_Kf : g_Qf;
    __nv_bfloat16* Ph = arr ? g_Kh : g_Qh;
    __nv_bfloat16* Pl = arr ? g_Kl : g_Ql;
    const size_t base = ((size_t)bh * T + t) * DH;
    const float u1 = P[base + d], u2 = P[base + d + 32];
    const float c = cosT[t * DH + d], s = sinT[t * DH + d];
    float o1 = u1 * c - u2 * s;
    float o2 = u2 * c + u1 * s;
    if (arr == 0) { o1 *= 0.125f; o2 *= 0.125f; }
    __nv_bfloat16 h1 = __float2bfloat16_rn(o1), h2 = __float2bfloat16_rn(o2);
    Ph[base + d]      = h1;
    Pl[base + d]      = __float2bfloat16_rn(o1 - __bfloat162float(h1));
    Ph[base + d + 32] = h2;
    Pl[base + d + 32] = __float2bfloat16_rn(o2 - __bfloat162float(h2));
}

// ---------------------------------------------------------------------------
// Flash attention, split-bf16 HMMA. CTA = 256 thr (8 warps), 128 query rows;
// 3-stage cp.async K/V pipeline, one sync per tile. MMAs interleaved across
// 4 accumulators (np processed in pairs, term-major).
// ---------------------------------------------------------------------------
constexpr int FPITCH = 72;                    // halves/row
constexpr int FTILE  = 64 * FPITCH;
constexpr int FSTAGE = 4 * FTILE;             // Kh,Kl,Vh,Vl
constexpr int FSTAGES = 3;
constexpr int FSMEM  = FSTAGES * FSTAGE * 2;  // 110592 bytes

__global__ __launch_bounds__(256, 1)
void flash_bf16()
{
    extern __shared__ __nv_bfloat16 fsm[];
    const int tid = threadIdx.x, lane = tid & 31, w = tid >> 5;
    const int g = lane >> 2, q = lane & 3;
    const int seg = lane >> 3, l7 = lane & 7;
    const int bh = blockIdx.y, q0 = blockIdx.x * 128;
    const size_t hb = (size_t)bh * T * DH;
    const unsigned sbase = (unsigned)__cvta_generic_to_shared(fsm);

    // Q fragments straight from gmem
    unsigned qh[4][4], ql[4][4];
    {
        const unsigned* Qh32 = (const unsigned*)(g_Qh + hb);
        const unsigned* Ql32 = (const unsigned*)(g_Ql + hb);
        const int r0 = q0 + w * 16 + g;
#pragma unroll
        for (int ks = 0; ks < 4; ks++) {
            const int c = ks * 8 + q;
            qh[ks][0] = Qh32[r0 * 32 + c];
            qh[ks][1] = Qh32[(r0 + 8) * 32 + c];
            qh[ks][2] = Qh32[r0 * 32 + c + 4];
            qh[ks][3] = Qh32[(r0 + 8) * 32 + c + 4];
            ql[ks][0] = Ql32[r0 * 32 + c];
            ql[ks][1] = Ql32[(r0 + 8) * 32 + c];
            ql[ks][2] = Ql32[r0 * 32 + c + 4];
            ql[ks][3] = Ql32[(r0 + 8) * 32 + c + 4];
        }
    }

    float oacc[8][4];
#pragma unroll
    for (int a = 0; a < 8; a++)
#pragma unroll
        for (int b = 0; b < 4; b++) oacc[a][b] = 0.f;
    float m_i[2] = {-1e30f, -1e30f}, l_i[2] = {0.f, 0.f};

    auto loadKV = [&](int stage, int n0) {
        unsigned sb = sbase + stage * FSTAGE * 2;
        const __nv_bfloat16* srcs[4] = {
            g_Kh + hb + (size_t)n0 * DH, g_Kl + hb + (size_t)n0 * DH,
            g_Vh + hb + (size_t)n0 * DH, g_Vl + hb + (size_t)n0 * DH };
#pragma unroll
        for (int a = 0; a < 4; a++)
#pragma unroll
            for (int i = 0; i < 2; i++) {
                int cid = tid + 256 * i;              // 0..511
                int r = cid >> 3, c = cid & 7;
                cp16(sb + (a * FTILE + r * FPITCH + c * 8) * 2, srcs[a] + r * 64 + c * 8);
            }
    };

    constexpr int NIT = T / 64;        // 32
    loadKV(0, 0);  CP_COMMIT();
    loadKV(1, 64); CP_COMMIT();

    for (int it = 0; it < NIT; ++it) {
        CP_WAIT_G1();
        __syncthreads();
        if (it + 2 < NIT) loadKV((it + 2) % 3, (it + 2) * 64);
        CP_COMMIT();

        unsigned sb = sbase + (it % 3) * FSTAGE * 2;
        unsigned kh = sb, kl = sb + FTILE * 2;
        unsigned vh = sb + 2 * FTILE * 2, vl = sb + 3 * FTILE * 2;

        // ---- S = Q @ K^T : np in pairs, term-major across 4 accumulators ---
        float sacc[8][4];
#pragma unroll
        for (int a = 0; a < 8; a++)
#pragma unroll
            for (int b = 0; b < 4; b++) sacc[a][b] = 0.f;
#pragma unroll
        for (int ks = 0; ks < 4; ks++) {
            const int kb = ks * 16;
#pragma unroll
            for (int npp = 0; npp < 2; npp++) {
                unsigned bkh[2][4], bkl[2][4];
#pragma unroll
                for (int j = 0; j < 2; j++) {
                    const int np = 2 * npp + j;
                    const int nr = np * 16 + l7 + ((seg >> 1) & 1) * 8;
                    const int kc = kb + (seg & 1) * 8;
                    const unsigned off = (nr * FPITCH + kc) * 2;
                    ldsm4(bkh[j], kh + off);
                    ldsm4(bkl[j], kl + off);
                }
                float* a0 = sacc[4 * npp + 0];
                float* a1 = sacc[4 * npp + 1];
                float* a2 = sacc[4 * npp + 2];
                float* a3 = sacc[4 * npp + 3];
                // hi*hi
                mma16816(a0, qh[ks], bkh[0]);
                mma16816(a1, qh[ks], bkh[0] + 2);
                mma16816(a2, qh[ks], bkh[1]);
                mma16816(a3, qh[ks], bkh[1] + 2);
                // hi*lo
                mma16816(a0, qh[ks], bkl[0]);
                mma16816(a1, qh[ks], bkl[0] + 2);
                mma16816(a2, qh[ks], bkl[1]);
                mma16816(a3, qh[ks], bkl[1] + 2);
                // lo*hi
                mma16816(a0, ql[ks], bkh[0]);
                mma16816(a1, ql[ks], bkh[0] + 2);
                mma16816(a2, ql[ks], bkh[1]);
                mma16816(a3, ql[ks], bkh[1] + 2);
            }
        }

        // ---- online softmax (rows g, g+8; reduce across quad lanes) ----
#pragma unroll
        for (int r = 0; r < 2; r++) {
            float mx = -1e30f;
#pragma unroll
            for (int nt = 0; nt < 8; nt++)
                mx = fmaxf(mx, fmaxf(sacc[nt][2 * r], sacc[nt][2 * r + 1]));
            mx = fmaxf(mx, __shfl_xor_sync(0xffffffffu, mx, 1));
            mx = fmaxf(mx, __shfl_xor_sync(0xffffffffu, mx, 2));
            const float mnew = fmaxf(m_i[r], mx);
            const float corr = __expf(m_i[r] - mnew);
            m_i[r] = mnew;
            float rs = 0.f;
#pragma unroll
            for (int nt = 0; nt < 8; nt++) {
                sacc[nt][2 * r]     = __expf(sacc[nt][2 * r] - mnew);
                sacc[nt][2 * r + 1] = __expf(sacc[nt][2 * r + 1] - mnew);
                rs += sacc[nt][2 * r] + sacc[nt][2 * r + 1];
            }
            rs += __shfl_xor_sync(0xffffffffu, rs, 1);
            rs += __shfl_xor_sync(0xffffffffu, rs, 2);
            l_i[r] = l_i[r] * corr + rs;
#pragma unroll
            for (int nt = 0; nt < 8; nt++) {
                oacc[nt][2 * r]     *= corr;
                oacc[nt][2 * r + 1] *= corr;
            }
        }

        // ---- pack P hi/lo; S C-frag layout == PV A-frag layout ----
        unsigned ph[16], pl[16];
#pragma unroll
        for (int nt = 0; nt < 8; nt++)
#pragma unroll
            for (int hf = 0; hf < 2; hf++) {
                const float p0 = sacc[nt][2 * hf], p1 = sacc[nt][2 * hf + 1];
                const __nv_bfloat16 b0 = __float2bfloat16_rn(p0);
                const __nv_bfloat16 b1 = __float2bfloat16_rn(p1);
                __nv_bfloat162 hi2 = __halves2bfloat162(b0, b1);
                ph[nt * 2 + hf] = *reinterpret_cast<unsigned*>(&hi2);
                pl[nt * 2 + hf] = pack2f(p0 - __bfloat162float(b0), p1 - __bfloat162float(b1));
            }

        // ---- O += P @ V : np in pairs, term-major across 4 accumulators ----
#pragma unroll
        for (int ks = 0; ks < 4; ks++) {
            const unsigned* aP  = &ph[4 * ks];
            const unsigned* aPl = &pl[4 * ks];
#pragma unroll
            for (int npp = 0; npp < 2; npp++) {
                unsigned bvh[2][4], bvl[2][4];
#pragma unroll
                for (int j = 0; j < 2; j++) {
                    const int np = 2 * npp + j;
                    const int vr = ks * 16 + l7 + (seg & 1) * 8;
                    const int vc = np * 16 + ((seg >> 1) & 1) * 8;
                    const unsigned off = (vr * FPITCH + vc) * 2;
                    ldsm4t(bvh[j], vh + off);
                    ldsm4t(bvl[j], vl + off);
                }
                float* a0 = oacc[4 * npp + 0];
                float* a1 = oacc[4 * npp + 1];
                float* a2 = oacc[4 * npp + 2];
                float* a3 = oacc[4 * npp + 3];
                // P_hi * V_hi
                mma16816(a0, aP, bvh[0]);
                mma16816(a1, aP, bvh[0] + 2);
                mma16816(a2, aP, bvh[1]);
                mma16816(a3, aP, bvh[1] + 2);
                // P_hi * V_lo
                mma16816(a0, aP, bvl[0]);
                mma16816(a1, aP, bvl[0] + 2);
                mma16816(a2, aP, bvl[1]);
                mma16816(a3, aP, bvl[1] + 2);
                // P_lo * V_hi
                mma16816(a0, aPl, bvh[0]);
                mma16816(a1, aPl, bvh[0] + 2);
                mma16816(a2, aPl, bvh[1]);
                mma16816(a3, aPl, bvh[1] + 2);
            }
        }
    }

    // ---- epilogue: normalize, split, store pre-split AO for proj GEMM ----
    const int b = bh >> 4, h = bh & 15;
#pragma unroll
    for (int r = 0; r < 2; r++) {
        const float inv = 1.f / l_i[r];
        const int t = q0 + w * 16 + g + r * 8;
        const size_t base = ((size_t)(b * T + t)) * Dm + h * DH;
#pragma unroll
        for (int nt = 0; nt < 8; nt++) {
            const float v0 = oacc[nt][2 * r] * inv;
            const float v1 = oacc[nt][2 * r + 1] * inv;
            const __nv_bfloat16 h0 = __float2bfloat16_rn(v0);
            const __nv_bfloat16 h1 = __float2bfloat16_rn(v1);
            *reinterpret_cast<__nv_bfloat162*>(g_AOh + base + nt * 8 + 2 * q) =
                __halves2bfloat162(h0, h1);
            *reinterpret_cast<__nv_bfloat162*>(g_AOl + base + nt * 8 + 2 * q) =
                __floats2bfloat162_rn(v0 - __bfloat162float(h0), v1 - __bfloat162float(h1));
        }
    }
}

// ---------------------------------------------------------------------------
extern "C" void kernel_launch(void* const* d_in, const int* in_sizes, int n_in,
                              void* d_out, int out_size)
{
    (void)in_sizes; (void)n_in; (void)out_size;
    const float* x     = (const float*)d_in[0];
    const float* Wqkv  = (const float*)d_in[1];
    const float* bqkv  = (const float*)d_in[2];
    const float* Wproj = (const float*)d_in[3];
    const float* bproj = (const float*)d_in[4];
    const float* cosT  = (const float*)d_in[5];
    const float* sinT  = (const float*)d_in[6];
    float* out = (float*)d_out;

    cudaFuncSetAttribute(gemm_bf16<0>, cudaFuncAttributeMaxDynamicSharedMemorySize, GSMEM);
    cudaFuncSetAttribute(gemm_bf16<1>, cudaFuncAttributeMaxDynamicSharedMemorySize, GSMEM);
    cudaFuncSetAttribute(flash_bf16,   cudaFuncAttributeMaxDynamicSharedMemorySize, FSMEM);

    split4_kernel<0><<<(M * KD / 4 + 255) / 256, 256>>>((const float4*)x, M * KD / 4);
    split4_kernel<1><<<(KD * NQKV / 4 + 255) / 256, 256>>>((const float4*)Wqkv, KD * NQKV / 4);
    split4_kernel<2><<<(KD * Dm / 4 + 255) / 256, 256>>>((const float4*)Wproj, KD * Dm / 4);

    gemm_bf16<0><<<dim3(NQKV / 128, M / 128), 256, GSMEM>>>(bqkv, nullptr, NQKV);

    rope_split_kernel<<<(2 * BHn * T * 32) / 256, 256>>>(cosT, sinT);

    flash_bf16<<<dim3(T / 128, BHn), 256, FSMEM>>>();

    gemm_bf16<1><<<dim3(Dm / 128, M / 128), 256, GSMEM>>>(bproj, out, Dm);
}